// round 1
// baseline (speedup 1.0000x reference)
#include <cuda_runtime.h>
#include <math.h>

#define BMAX 65536
#define BN_EPS 1e-5f

// ---------------- scratch (static device globals; no runtime allocation) -----
static __device__ float g_q[BMAX * 4];                 // 1 MB   quantum outputs
static __device__ float g_h2[(size_t)BMAX * 256];      // 64 MB  fc2 pre-bn output
static __device__ float g_w2t[128 * 256];              // W2 transposed [k][c]
static __device__ float g_w3t[256 * 256];              // W3 transposed [k][c]
static __device__ float g_sumz[4];
static __device__ float g_sumzz[16];
static __device__ float g_sum2[256];
static __device__ float g_sumsq2[256];
static __device__ float g_sc1[128], g_sh1[128];
static __device__ float g_sc2[256], g_sh2[256];

// ---------------- zero accumulators ------------------------------------------
__global__ void k_zero() {
    int t = threadIdx.x;
    if (t < 4)  g_sumz[t] = 0.f;
    if (t < 16) g_sumzz[t] = 0.f;
    if (t < 256) { g_sum2[t] = 0.f; g_sumsq2[t] = 0.f; }
}

// ---------------- transpose weights to K-major --------------------------------
__global__ void k_prep(const float* __restrict__ w2, const float* __restrict__ w3) {
    int total = 128 * 256 + 256 * 256;
    for (int i = blockIdx.x * blockDim.x + threadIdx.x; i < total;
         i += gridDim.x * blockDim.x) {
        if (i < 128 * 256) {
            int k = i >> 8, c = i & 255;          // i = k*256+c
            g_w2t[i] = w2[c * 128 + k];
        } else {
            int j = i - 128 * 256;
            int k = j >> 8, c = j & 255;
            g_w3t[j] = w3[c * 256 + k];
        }
    }
}

// ---------------- quantum simulator + q statistics ----------------------------
__global__ void k_sim(const float* __restrict__ x, const float* __restrict__ qp, int Bc) {
    int t = blockIdx.x * blockDim.x + threadIdx.x;
    float z[4] = {0.f, 0.f, 0.f, 0.f};
    if (t < Bc) {
        float xr[4];
        #pragma unroll
        for (int i = 0; i < 4; i++) xr[i] = x[t * 4 + i];

        float re[16], im[16];
        #pragma unroll
        for (int i = 0; i < 16; i++) { re[i] = 0.f; im[i] = 0.f; }
        re[0] = 1.f;

        #pragma unroll
        for (int d = 0; d < 3; d++) {
            // RY(x_i + theta) on each qubit (qubit i = bit 3-i)
            #pragma unroll
            for (int i = 0; i < 4; i++) {
                float s, c;
                sincosf(0.5f * (xr[i] + qp[d * 8 + i]), &s, &c);
                int m = 1 << (3 - i);
                #pragma unroll
                for (int idx = 0; idx < 16; idx++) {
                    if ((idx & m) == 0) {
                        int p = idx | m;
                        float a0r = re[idx], a0i = im[idx];
                        float a1r = re[p],  a1i = im[p];
                        re[idx] = c * a0r - s * a1r;  im[idx] = c * a0i - s * a1i;
                        re[p]   = s * a0r + c * a1r;  im[p]   = s * a0i + c * a1i;
                    }
                }
            }
            // CNOT ring (i -> (i+1)%4)
            #pragma unroll
            for (int i = 0; i < 4; i++) {
                int cm = 1 << (3 - i);
                int tm = 1 << (3 - ((i + 1) & 3));
                #pragma unroll
                for (int idx = 0; idx < 16; idx++) {
                    if ((idx & cm) && !(idx & tm)) {
                        int p = idx | tm;
                        float tr = re[idx]; re[idx] = re[p]; re[p] = tr;
                        float ti = im[idx]; im[idx] = im[p]; im[p] = ti;
                    }
                }
            }
            // RZ(theta) shared params
            #pragma unroll
            for (int i = 0; i < 4; i++) {
                float s, c;
                sincosf(0.5f * qp[d * 8 + 4 + i], &s, &c);
                int m = 1 << (3 - i);
                #pragma unroll
                for (int idx = 0; idx < 16; idx++) {
                    float pi = (idx & m) ? s : -s;
                    float r0 = re[idx], i0 = im[idx];
                    re[idx] = r0 * c - i0 * pi;
                    im[idx] = i0 * c + r0 * pi;
                }
            }
        }
        #pragma unroll
        for (int i = 0; i < 4; i++) {
            int m = 1 << (3 - i);
            float acc = 0.f;
            #pragma unroll
            for (int idx = 0; idx < 16; idx++) {
                float p = re[idx] * re[idx] + im[idx] * im[idx];
                acc += (idx & m) ? -p : p;
            }
            z[i] = acc;
        }
        *(float4*)(g_q + (size_t)t * 4) = make_float4(z[0], z[1], z[2], z[3]);
    }

    // accumulate sum(z) and sum(z z^T) for analytic bn1 stats
    float vals[20];
    #pragma unroll
    for (int a = 0; a < 4; a++) vals[a] = z[a];
    #pragma unroll
    for (int a = 0; a < 4; a++)
        #pragma unroll
        for (int b = 0; b < 4; b++) vals[4 + a * 4 + b] = z[a] * z[b];
    #pragma unroll
    for (int v = 0; v < 20; v++) {
        #pragma unroll
        for (int off = 16; off > 0; off >>= 1)
            vals[v] += __shfl_xor_sync(0xffffffffu, vals[v], off);
    }
    if ((threadIdx.x & 31) == 0) {
        #pragma unroll
        for (int a = 0; a < 4; a++) atomicAdd(&g_sumz[a], vals[a]);
        #pragma unroll
        for (int v = 0; v < 16; v++) atomicAdd(&g_sumzz[v], vals[4 + v]);
    }
}

// ---------------- bn1 params (analytic: h1 affine in q) -----------------------
__global__ void k_bn1(const float* __restrict__ w1, const float* __restrict__ g,
                      const float* __restrict__ b, float binv) {
    int j = threadIdx.x;  // 128 threads
    float mu[4], C[16];
    #pragma unroll
    for (int a = 0; a < 4; a++) mu[a] = g_sumz[a] * binv;
    #pragma unroll
    for (int a = 0; a < 4; a++)
        #pragma unroll
        for (int c = 0; c < 4; c++)
            C[a * 4 + c] = g_sumzz[a * 4 + c] * binv - mu[a] * mu[c];
    float w[4];
    #pragma unroll
    for (int a = 0; a < 4; a++) w[a] = w1[j * 4 + a];
    float m0 = 0.f, v = 0.f;
    #pragma unroll
    for (int a = 0; a < 4; a++) {
        m0 += w[a] * mu[a];
        #pragma unroll
        for (int c = 0; c < 4; c++) v += w[a] * w[c] * C[a * 4 + c];
    }
    float sc = g[j] * rsqrtf(v + BN_EPS);
    g_sc1[j] = sc;
    g_sh1[j] = b[j] - sc * m0;   // fc1 bias cancels exactly
}

// ---------------- bn2 params from fused fc2 stats -----------------------------
__global__ void k_bn2(const float* __restrict__ g, const float* __restrict__ b, float binv) {
    int j = threadIdx.x;  // 256 threads
    float mean = g_sum2[j] * binv;
    float var  = g_sumsq2[j] * binv - mean * mean;
    float sc = g[j] * rsqrtf(var + BN_EPS);
    g_sc2[j] = sc;
    g_sh2[j] = b[j] - sc * mean; // fc2 bias cancels exactly
}

// ---------------- fc2 GEMM: h2 = relu(bn1(q@W1^T)) @ W2^T  (+ fused stats) ----
__global__ void __launch_bounds__(512, 1)
k_fc2(const float* __restrict__ w1, int Bc) {
    extern __shared__ float sm[];
    float* As = sm;            // [128 rows][128 k]
    float* Bs = sm + 16384;    // [128 k][128 c]
    __shared__ float qs[512], w1s[512], sc1[128], sh1[128];

    int tid = threadIdx.x;
    int row0 = blockIdx.x * 128;
    int bc = blockIdx.y;       // col tile 0/1

    {   // stage small operands
        int a = tid >> 7, f = tid & 127;
        w1s[a * 128 + f] = w1[f * 4 + a];
        if (tid < 128) {
            int r = row0 + tid;
            float4 q = (r < Bc) ? *(const float4*)(g_q + (size_t)r * 4)
                                : make_float4(0.f, 0.f, 0.f, 0.f);
            *(float4*)(qs + tid * 4) = q;
            sc1[tid] = g_sc1[tid];
            sh1[tid] = g_sh1[tid];
        }
    }
    __syncthreads();

    // A-stage: compute h1r tile in smem (row-major over k)
    #pragma unroll
    for (int i = 0; i < 32; i++) {
        int e = tid + i * 512;          // e = r*128 + f
        int r = e >> 7, f = e & 127;
        float d = qs[r * 4] * w1s[f] + qs[r * 4 + 1] * w1s[128 + f]
                + qs[r * 4 + 2] * w1s[256 + f] + qs[r * 4 + 3] * w1s[384 + f];
        As[e] = fmaxf(fmaf(sc1[f], d, sh1[f]), 0.f);
    }
    // B-stage: W2T tile (coalesced, conflict-free)
    #pragma unroll
    for (int i = 0; i < 8; i++) {
        int idx4 = tid + i * 512;
        int k = idx4 >> 5, cq = idx4 & 31;
        *(float4*)(Bs + k * 128 + cq * 4) =
            *(const float4*)(g_w2t + k * 256 + bc * 128 + cq * 4);
    }
    __syncthreads();

    int tr = tid >> 5, tc = tid & 31;
    float acc[8][4];
    #pragma unroll
    for (int i = 0; i < 8; i++)
        #pragma unroll
        for (int j = 0; j < 4; j++) acc[i][j] = 0.f;

    #pragma unroll 4
    for (int k4 = 0; k4 < 32; k4++) {
        float4 a[8], bfr[4];
        #pragma unroll
        for (int i = 0; i < 8; i++) {
            int r = (i < 4) ? (tr * 4 + i) : (64 + tr * 4 + i - 4);
            a[i] = *(const float4*)(As + r * 128 + k4 * 4);
        }
        #pragma unroll
        for (int jj = 0; jj < 4; jj++)
            bfr[jj] = *(const float4*)(Bs + (k4 * 4 + jj) * 128 + tc * 4);
        #pragma unroll
        for (int kk = 0; kk < 4; kk++) {
            float bx = ((const float*)&bfr[kk])[0];
            float by = ((const float*)&bfr[kk])[1];
            float bz = ((const float*)&bfr[kk])[2];
            float bw = ((const float*)&bfr[kk])[3];
            #pragma unroll
            for (int i = 0; i < 8; i++) {
                float av = ((const float*)&a[i])[kk];
                acc[i][0] += av * bx;
                acc[i][1] += av * by;
                acc[i][2] += av * bz;
                acc[i][3] += av * bw;
            }
        }
    }

    __syncthreads();  // reuse As region for stats reduction
    float* redS = sm;          // [16][128]
    float* redQ = sm + 2048;   // [16][128]

    float cs[4] = {0.f, 0.f, 0.f, 0.f}, cq2[4] = {0.f, 0.f, 0.f, 0.f};
    #pragma unroll
    for (int i = 0; i < 8; i++) {
        int r = (i < 4) ? (tr * 4 + i) : (64 + tr * 4 + i - 4);
        int grow = row0 + r;
        if (grow < Bc) {
            float4 v = make_float4(acc[i][0], acc[i][1], acc[i][2], acc[i][3]);
            *(float4*)(g_h2 + (size_t)grow * 256 + bc * 128 + tc * 4) = v;
            #pragma unroll
            for (int j = 0; j < 4; j++) {
                cs[j]  += acc[i][j];
                cq2[j] += acc[i][j] * acc[i][j];
            }
        }
    }
    #pragma unroll
    for (int j = 0; j < 4; j++) {
        redS[tr * 128 + tc * 4 + j] = cs[j];
        redQ[tr * 128 + tc * 4 + j] = cq2[j];
    }
    __syncthreads();
    if (tid < 128) {
        float s = 0.f, q = 0.f;
        #pragma unroll
        for (int t16 = 0; t16 < 16; t16++) {
            s += redS[t16 * 128 + tid];
            q += redQ[t16 * 128 + tid];
        }
        atomicAdd(&g_sum2[bc * 128 + tid], s);
        atomicAdd(&g_sumsq2[bc * 128 + tid], q);
    }
}

// ---------------- fc3 GEMM: out = tanh(relu(bn2(h2)) @ W3^T + b3) -------------
__global__ void __launch_bounds__(512, 1)
k_fc3(const float* __restrict__ b3, float* __restrict__ out, int Bc) {
    extern __shared__ float sm[];
    float* As = sm;
    float* Bs = sm + 16384;

    int tid = threadIdx.x;
    int row0 = blockIdx.x * 128;
    int bc = blockIdx.y;
    int tr = tid >> 5, tc = tid & 31;

    float acc[8][4];
    #pragma unroll
    for (int i = 0; i < 8; i++)
        #pragma unroll
        for (int j = 0; j < 4; j++) acc[i][j] = 0.f;

    for (int ck = 0; ck < 2; ck++) {
        if (ck) __syncthreads();
        // A-load with bn2+relu applied
        #pragma unroll
        for (int i = 0; i < 8; i++) {
            int idx4 = tid + i * 512;
            int r = idx4 >> 5, kq = idx4 & 31;
            int grow = row0 + r;
            float4 h = (grow < Bc)
                ? *(const float4*)(g_h2 + (size_t)grow * 256 + ck * 128 + kq * 4)
                : make_float4(0.f, 0.f, 0.f, 0.f);
            float4 sc = *(const float4*)(g_sc2 + ck * 128 + kq * 4);
            float4 sh = *(const float4*)(g_sh2 + ck * 128 + kq * 4);
            float4 v;
            v.x = fmaxf(fmaf(h.x, sc.x, sh.x), 0.f);
            v.y = fmaxf(fmaf(h.y, sc.y, sh.y), 0.f);
            v.z = fmaxf(fmaf(h.z, sc.z, sh.z), 0.f);
            v.w = fmaxf(fmaf(h.w, sc.w, sh.w), 0.f);
            *(float4*)(As + r * 128 + kq * 4) = v;
        }
        // B-load
        #pragma unroll
        for (int i = 0; i < 8; i++) {
            int idx4 = tid + i * 512;
            int k = idx4 >> 5, cq = idx4 & 31;
            *(float4*)(Bs + k * 128 + cq * 4) =
                *(const float4*)(g_w3t + (ck * 128 + k) * 256 + bc * 128 + cq * 4);
        }
        __syncthreads();

        #pragma unroll 4
        for (int k4 = 0; k4 < 32; k4++) {
            float4 a[8], bfr[4];
            #pragma unroll
            for (int i = 0; i < 8; i++) {
                int r = (i < 4) ? (tr * 4 + i) : (64 + tr * 4 + i - 4);
                a[i] = *(const float4*)(As + r * 128 + k4 * 4);
            }
            #pragma unroll
            for (int jj = 0; jj < 4; jj++)
                bfr[jj] = *(const float4*)(Bs + (k4 * 4 + jj) * 128 + tc * 4);
            #pragma unroll
            for (int kk = 0; kk < 4; kk++) {
                float bx = ((const float*)&bfr[kk])[0];
                float by = ((const float*)&bfr[kk])[1];
                float bz = ((const float*)&bfr[kk])[2];
                float bw = ((const float*)&bfr[kk])[3];
                #pragma unroll
                for (int i = 0; i < 8; i++) {
                    float av = ((const float*)&a[i])[kk];
                    acc[i][0] += av * bx;
                    acc[i][1] += av * by;
                    acc[i][2] += av * bz;
                    acc[i][3] += av * bw;
                }
            }
        }
    }

    float4 bias = *(const float4*)(b3 + bc * 128 + tc * 4);
    #pragma unroll
    for (int i = 0; i < 8; i++) {
        int r = (i < 4) ? (tr * 4 + i) : (64 + tr * 4 + i - 4);
        int grow = row0 + r;
        if (grow < Bc) {
            float4 o;
            o.x = tanhf(acc[i][0] + bias.x);
            o.y = tanhf(acc[i][1] + bias.y);
            o.z = tanhf(acc[i][2] + bias.z);
            o.w = tanhf(acc[i][3] + bias.w);
            *(float4*)(out + (size_t)grow * 256 + bc * 128 + tc * 4) = o;
        }
    }
}

// ---------------- launch ------------------------------------------------------
extern "C" void kernel_launch(void* const* d_in, const int* in_sizes, int n_in,
                              void* d_out, int out_size) {
    const float* x     = (const float*)d_in[0];
    const float* qp    = (const float*)d_in[1];
    const float* fc1_w = (const float*)d_in[2];
    // d_in[3] = fc1_b (cancels in bn1), d_in[7] = fc2_b (cancels in bn2)
    const float* bn1_g = (const float*)d_in[4];
    const float* bn1_b = (const float*)d_in[5];
    const float* fc2_w = (const float*)d_in[6];
    const float* bn2_g = (const float*)d_in[8];
    const float* bn2_b = (const float*)d_in[9];
    const float* fc3_w = (const float*)d_in[10];
    const float* fc3_b = (const float*)d_in[11];
    float* out = (float*)d_out;

    int Bc = in_sizes[0] / 4;
    if (Bc > BMAX) Bc = BMAX;
    float binv = 1.0f / (float)Bc;

    const int SMEM = 2 * 128 * 128 * (int)sizeof(float);  // 128 KB
    cudaFuncSetAttribute(k_fc2, cudaFuncAttributeMaxDynamicSharedMemorySize, SMEM);
    cudaFuncSetAttribute(k_fc3, cudaFuncAttributeMaxDynamicSharedMemorySize, SMEM);

    k_zero<<<1, 256>>>();
    k_prep<<<192, 512>>>(fc2_w, fc3_w);
    k_sim<<<(Bc + 255) / 256, 256>>>(x, qp, Bc);
    k_bn1<<<1, 128>>>(fc1_w, bn1_g, bn1_b, binv);

    dim3 gfc((Bc + 127) / 128, 2);
    k_fc2<<<gfc, 512, SMEM>>>(fc1_w, Bc);
    k_bn2<<<1, 256>>>(bn2_g, bn2_b, binv);
    k_fc3<<<gfc, 512, SMEM>>>(fc3_b, out, Bc);
}

// round 2
// speedup vs baseline: 1.8418x; 1.8418x over previous
#include <cuda_runtime.h>
#include <math.h>
#include <stdint.h>

#define BMAX 65536
#define BN_EPS 1e-5f
#define SA 132   // smem tile stride (words): bank = (4*row + col) % 32 -> conflict-free frags

// ---------------- scratch (static device globals; no runtime allocation) -----
static __device__ float g_q[BMAX * 4];                 // 1 MB   quantum outputs
static __device__ float g_h2[(size_t)BMAX * 256];      // 64 MB  fc2 pre-bn output
static __device__ float g_sumz[4];
static __device__ float g_sumzz[16];
static __device__ float g_sum2[256];
static __device__ float g_sumsq2[256];
static __device__ float g_sc1[128], g_sh1[128];
static __device__ float g_sc2[256], g_sh2[256];

// ---------------- tf32 helpers ------------------------------------------------
__device__ __forceinline__ float to_tf32(float x) {
    uint32_t u;
    asm("cvt.rna.tf32.f32 %0, %1;" : "=r"(u) : "f"(x));
    return __uint_as_float(u);
}

__device__ __forceinline__ void mma_tf32(float* c, const uint32_t* a, const uint32_t* b) {
    asm volatile(
        "mma.sync.aligned.m16n8k8.row.col.f32.tf32.tf32.f32 "
        "{%0,%1,%2,%3}, {%4,%5,%6,%7}, {%8,%9}, {%0,%1,%2,%3};"
        : "+f"(c[0]), "+f"(c[1]), "+f"(c[2]), "+f"(c[3])
        : "r"(a[0]), "r"(a[1]), "r"(a[2]), "r"(a[3]),
          "r"(b[0]), "r"(b[1]));
}

// ---------------- zero accumulators ------------------------------------------
__global__ void k_zero() {
    int t = threadIdx.x;
    if (t < 4)  g_sumz[t] = 0.f;
    if (t < 16) g_sumzz[t] = 0.f;
    if (t < 256) { g_sum2[t] = 0.f; g_sumsq2[t] = 0.f; }
}

// ---------------- quantum simulator + q statistics ----------------------------
__global__ void k_sim(const float* __restrict__ x, const float* __restrict__ qp, int Bc) {
    int t = blockIdx.x * blockDim.x + threadIdx.x;
    float z[4] = {0.f, 0.f, 0.f, 0.f};
    if (t < Bc) {
        float xr[4];
        #pragma unroll
        for (int i = 0; i < 4; i++) xr[i] = x[t * 4 + i];

        float re[16], im[16];
        #pragma unroll
        for (int i = 0; i < 16; i++) { re[i] = 0.f; im[i] = 0.f; }
        re[0] = 1.f;

        #pragma unroll
        for (int d = 0; d < 3; d++) {
            #pragma unroll
            for (int i = 0; i < 4; i++) {
                float s, c;
                sincosf(0.5f * (xr[i] + qp[d * 8 + i]), &s, &c);
                int m = 1 << (3 - i);
                #pragma unroll
                for (int idx = 0; idx < 16; idx++) {
                    if ((idx & m) == 0) {
                        int p = idx | m;
                        float a0r = re[idx], a0i = im[idx];
                        float a1r = re[p],  a1i = im[p];
                        re[idx] = c * a0r - s * a1r;  im[idx] = c * a0i - s * a1i;
                        re[p]   = s * a0r + c * a1r;  im[p]   = s * a0i + c * a1i;
                    }
                }
            }
            #pragma unroll
            for (int i = 0; i < 4; i++) {
                int cm = 1 << (3 - i);
                int tm = 1 << (3 - ((i + 1) & 3));
                #pragma unroll
                for (int idx = 0; idx < 16; idx++) {
                    if ((idx & cm) && !(idx & tm)) {
                        int p = idx | tm;
                        float tr = re[idx]; re[idx] = re[p]; re[p] = tr;
                        float ti = im[idx]; im[idx] = im[p]; im[p] = ti;
                    }
                }
            }
            #pragma unroll
            for (int i = 0; i < 4; i++) {
                float s, c;
                sincosf(0.5f * qp[d * 8 + 4 + i], &s, &c);
                int m = 1 << (3 - i);
                #pragma unroll
                for (int idx = 0; idx < 16; idx++) {
                    float pi = (idx & m) ? s : -s;
                    float r0 = re[idx], i0 = im[idx];
                    re[idx] = r0 * c - i0 * pi;
                    im[idx] = i0 * c + r0 * pi;
                }
            }
        }
        #pragma unroll
        for (int i = 0; i < 4; i++) {
            int m = 1 << (3 - i);
            float acc = 0.f;
            #pragma unroll
            for (int idx = 0; idx < 16; idx++) {
                float p = re[idx] * re[idx] + im[idx] * im[idx];
                acc += (idx & m) ? -p : p;
            }
            z[i] = acc;
        }
        *(float4*)(g_q + (size_t)t * 4) = make_float4(z[0], z[1], z[2], z[3]);
    }

    float vals[20];
    #pragma unroll
    for (int a = 0; a < 4; a++) vals[a] = z[a];
    #pragma unroll
    for (int a = 0; a < 4; a++)
        #pragma unroll
        for (int b = 0; b < 4; b++) vals[4 + a * 4 + b] = z[a] * z[b];
    #pragma unroll
    for (int v = 0; v < 20; v++) {
        #pragma unroll
        for (int off = 16; off > 0; off >>= 1)
            vals[v] += __shfl_xor_sync(0xffffffffu, vals[v], off);
    }
    if ((threadIdx.x & 31) == 0) {
        #pragma unroll
        for (int a = 0; a < 4; a++) atomicAdd(&g_sumz[a], vals[a]);
        #pragma unroll
        for (int v = 0; v < 16; v++) atomicAdd(&g_sumzz[v], vals[4 + v]);
    }
}

// ---------------- bn1 params (analytic: h1 affine in q) -----------------------
__global__ void k_bn1(const float* __restrict__ w1, const float* __restrict__ g,
                      const float* __restrict__ b, float binv) {
    int j = threadIdx.x;  // 128 threads
    float mu[4], C[16];
    #pragma unroll
    for (int a = 0; a < 4; a++) mu[a] = g_sumz[a] * binv;
    #pragma unroll
    for (int a = 0; a < 4; a++)
        #pragma unroll
        for (int c = 0; c < 4; c++)
            C[a * 4 + c] = g_sumzz[a * 4 + c] * binv - mu[a] * mu[c];
    float w[4];
    #pragma unroll
    for (int a = 0; a < 4; a++) w[a] = w1[j * 4 + a];
    float m0 = 0.f, v = 0.f;
    #pragma unroll
    for (int a = 0; a < 4; a++) {
        m0 += w[a] * mu[a];
        #pragma unroll
        for (int c = 0; c < 4; c++) v += w[a] * w[c] * C[a * 4 + c];
    }
    float sc = g[j] * rsqrtf(v + BN_EPS);
    g_sc1[j] = sc;
    g_sh1[j] = b[j] - sc * m0;
}

// ---------------- bn2 params from fused fc2 stats -----------------------------
__global__ void k_bn2(const float* __restrict__ g, const float* __restrict__ b, float binv) {
    int j = threadIdx.x;  // 256 threads
    float mean = g_sum2[j] * binv;
    float var  = g_sumsq2[j] * binv - mean * mean;
    float sc = g[j] * rsqrtf(var + BN_EPS);
    g_sc2[j] = sc;
    g_sh2[j] = b[j] - sc * mean;
}

// ---------------- fc2: h2 = relu(bn1(q@W1^T)) @ W2^T  (tf32 mma, fused stats) -
__global__ void __launch_bounds__(512, 1)
k_fc2(const float* __restrict__ w1, const float* __restrict__ w2, int Bc) {
    extern __shared__ float sm[];
    float* As = sm;              // [128][SA]
    float* Bs = sm + 128 * SA;   // [128][SA]
    __shared__ float qs[512], w1s[512], sc1s[128], sh1s[128];
    __shared__ float redS[16 * 32], redQ[16 * 32];

    int tid = threadIdx.x;
    int row0 = blockIdx.x * 128;
    int bc = blockIdx.y;

    {
        int a = tid >> 7, f = tid & 127;
        w1s[a * 128 + f] = w1[f * 4 + a];
        if (tid < 128) {
            int r = row0 + tid;
            float4 q = (r < Bc) ? *(const float4*)(g_q + (size_t)r * 4)
                                : make_float4(0.f, 0.f, 0.f, 0.f);
            *(float4*)(qs + tid * 4) = q;
            sc1s[tid] = g_sc1[tid];
            sh1s[tid] = g_sh1[tid];
        }
    }
    __syncthreads();

    // A-stage: h1r computed on the fly, rounded to tf32
    #pragma unroll
    for (int i = 0; i < 32; i++) {
        int e = tid + i * 512;
        int r = e >> 7, f = e & 127;
        float v = 0.f;
        if (row0 + r < Bc) {
            float d = qs[r * 4] * w1s[f] + qs[r * 4 + 1] * w1s[128 + f]
                    + qs[r * 4 + 2] * w1s[256 + f] + qs[r * 4 + 3] * w1s[384 + f];
            v = fmaxf(fmaf(sc1s[f], d, sh1s[f]), 0.f);
        }
        As[r * SA + f] = to_tf32(v);
    }
    // B-stage: w2 is [256][128] row-major => exactly the col-major (n-major) operand
    #pragma unroll
    for (int i = 0; i < 8; i++) {
        int idx4 = tid + i * 512;
        int n = idx4 >> 5, kq = idx4 & 31;
        float4 w = *(const float4*)(w2 + (size_t)(bc * 128 + n) * 128 + kq * 4);
        float4 tw;
        tw.x = to_tf32(w.x); tw.y = to_tf32(w.y);
        tw.z = to_tf32(w.z); tw.w = to_tf32(w.w);
        *(float4*)(Bs + n * SA + kq * 4) = tw;
    }
    __syncthreads();

    int lane = tid & 31, wid = tid >> 5;
    int wr = wid >> 2, wc = wid & 3;
    int m0 = wr * 32, n0 = wc * 32;

    float acc[2][4][4];
    #pragma unroll
    for (int i = 0; i < 2; i++)
        #pragma unroll
        for (int j = 0; j < 4; j++)
            #pragma unroll
            for (int p = 0; p < 4; p++) acc[i][j][p] = 0.f;

    const uint32_t* Au = (const uint32_t*)As;
    const uint32_t* Bu = (const uint32_t*)Bs;
    int arow = m0 + (lane >> 2), acol = lane & 3;
    int brow = n0 + (lane >> 2), bk = lane & 3;

    #pragma unroll 8
    for (int k8 = 0; k8 < 16; k8++) {
        uint32_t a[2][4], b[4][2];
        #pragma unroll
        for (int i = 0; i < 2; i++) {
            int base = (arow + i * 16) * SA + k8 * 8 + acol;
            a[i][0] = Au[base];
            a[i][1] = Au[base + 8 * SA];
            a[i][2] = Au[base + 4];
            a[i][3] = Au[base + 8 * SA + 4];
        }
        #pragma unroll
        for (int j = 0; j < 4; j++) {
            int base = (brow + j * 8) * SA + k8 * 8 + bk;
            b[j][0] = Bu[base];
            b[j][1] = Bu[base + 4];
        }
        #pragma unroll
        for (int i = 0; i < 2; i++)
            #pragma unroll
            for (int j = 0; j < 4; j++)
                mma_tf32(acc[i][j], a[i], b[j]);
    }

    // epilogue: store h2 (float2, c0/c1 adjacent cols) + fused column stats
    float cs[4][2], cq[4][2];
    #pragma unroll
    for (int j = 0; j < 4; j++) { cs[j][0] = cs[j][1] = cq[j][0] = cq[j][1] = 0.f; }

    #pragma unroll
    for (int i = 0; i < 2; i++) {
        #pragma unroll
        for (int half = 0; half < 2; half++) {
            int grow = row0 + m0 + i * 16 + (lane >> 2) + half * 8;
            #pragma unroll
            for (int j = 0; j < 4; j++) {
                float v0 = acc[i][j][half * 2 + 0];
                float v1 = acc[i][j][half * 2 + 1];
                if (grow < Bc) {
                    *(float2*)(g_h2 + (size_t)grow * 256 + bc * 128 + n0 + j * 8 + (lane & 3) * 2)
                        = make_float2(v0, v1);
                }
                cs[j][0] += v0; cs[j][1] += v1;
                cq[j][0] += v0 * v0; cq[j][1] += v1 * v1;
            }
        }
    }
    // columns depend only on lane%4 -> reduce over lanes with stride >= 4
    #pragma unroll
    for (int j = 0; j < 4; j++)
        #pragma unroll
        for (int p = 0; p < 2; p++) {
            #pragma unroll
            for (int off = 4; off < 32; off <<= 1) {
                cs[j][p] += __shfl_xor_sync(0xffffffffu, cs[j][p], off);
                cq[j][p] += __shfl_xor_sync(0xffffffffu, cq[j][p], off);
            }
        }
    if (lane < 4) {
        #pragma unroll
        for (int j = 0; j < 4; j++)
            #pragma unroll
            for (int p = 0; p < 2; p++) {
                int c32 = j * 8 + lane * 2 + p;
                redS[wid * 32 + c32] = cs[j][p];
                redQ[wid * 32 + c32] = cq[j][p];
            }
    }
    __syncthreads();
    if (tid < 128) {
        int wcg = tid >> 5, c32 = tid & 31;
        float s = 0.f, q = 0.f;
        #pragma unroll
        for (int w = 0; w < 4; w++) {
            s += redS[(w * 4 + wcg) * 32 + c32];
            q += redQ[(w * 4 + wcg) * 32 + c32];
        }
        atomicAdd(&g_sum2[bc * 128 + tid], s);
        atomicAdd(&g_sumsq2[bc * 128 + tid], q);
    }
}

// ---------------- fc3: out = tanh(relu(bn2(h2)) @ W3^T + b3) (tf32 mma) -------
__global__ void __launch_bounds__(512, 1)
k_fc3(const float* __restrict__ w3, const float* __restrict__ b3,
      float* __restrict__ out, int Bc) {
    extern __shared__ float sm[];
    float* As = sm;
    float* Bs = sm + 128 * SA;
    __shared__ float sc2s[256], sh2s[256];

    int tid = threadIdx.x;
    if (tid < 256) { sc2s[tid] = g_sc2[tid]; sh2s[tid] = g_sh2[tid]; }

    int row0 = blockIdx.x * 128;
    int bc = blockIdx.y;
    int lane = tid & 31, wid = tid >> 5;
    int wr = wid >> 2, wc = wid & 3;
    int m0 = wr * 32, n0 = wc * 32;
    int arow = m0 + (lane >> 2), acol = lane & 3;
    int brow = n0 + (lane >> 2), bk = lane & 3;

    float acc[2][4][4];
    #pragma unroll
    for (int i = 0; i < 2; i++)
        #pragma unroll
        for (int j = 0; j < 4; j++)
            #pragma unroll
            for (int p = 0; p < 4; p++) acc[i][j][p] = 0.f;

    const uint32_t* Au = (const uint32_t*)As;
    const uint32_t* Bu = (const uint32_t*)Bs;

    for (int ck = 0; ck < 2; ck++) {
        __syncthreads();   // first iter: covers sc2s init; later: protects tiles
        // A-stage: bn2 + relu applied on load, tf32-rounded
        #pragma unroll
        for (int i = 0; i < 8; i++) {
            int idx4 = tid + i * 512;
            int r = idx4 >> 5, kq = idx4 & 31;
            int grow = row0 + r;
            float4 h = (grow < Bc)
                ? *(const float4*)(g_h2 + (size_t)grow * 256 + ck * 128 + kq * 4)
                : make_float4(0.f, 0.f, 0.f, 0.f);
            float4 sc = *(const float4*)(sc2s + ck * 128 + kq * 4);
            float4 sh = *(const float4*)(sh2s + ck * 128 + kq * 4);
            float4 v;
            v.x = to_tf32(fmaxf(fmaf(h.x, sc.x, sh.x), 0.f));
            v.y = to_tf32(fmaxf(fmaf(h.y, sc.y, sh.y), 0.f));
            v.z = to_tf32(fmaxf(fmaf(h.z, sc.z, sh.z), 0.f));
            v.w = to_tf32(fmaxf(fmaf(h.w, sc.w, sh.w), 0.f));
            *(float4*)(As + r * SA + kq * 4) = v;
        }
        // B-stage: w3 [256][256] row-major -> n-major operand, direct
        #pragma unroll
        for (int i = 0; i < 8; i++) {
            int idx4 = tid + i * 512;
            int n = idx4 >> 5, kq = idx4 & 31;
            float4 w = *(const float4*)(w3 + (size_t)(bc * 128 + n) * 256 + ck * 128 + kq * 4);
            float4 tw;
            tw.x = to_tf32(w.x); tw.y = to_tf32(w.y);
            tw.z = to_tf32(w.z); tw.w = to_tf32(w.w);
            *(float4*)(Bs + n * SA + kq * 4) = tw;
        }
        __syncthreads();

        #pragma unroll 8
        for (int k8 = 0; k8 < 16; k8++) {
            uint32_t a[2][4], b[4][2];
            #pragma unroll
            for (int i = 0; i < 2; i++) {
                int base = (arow + i * 16) * SA + k8 * 8 + acol;
                a[i][0] = Au[base];
                a[i][1] = Au[base + 8 * SA];
                a[i][2] = Au[base + 4];
                a[i][3] = Au[base + 8 * SA + 4];
            }
            #pragma unroll
            for (int j = 0; j < 4; j++) {
                int base = (brow + j * 8) * SA + k8 * 8 + bk;
                b[j][0] = Bu[base];
                b[j][1] = Bu[base + 4];
            }
            #pragma unroll
            for (int i = 0; i < 2; i++)
                #pragma unroll
                for (int j = 0; j < 4; j++)
                    mma_tf32(acc[i][j], a[i], b[j]);
        }
    }

    // epilogue: +bias, tanh, float2 stores
    #pragma unroll
    for (int j = 0; j < 4; j++) {
        int col = bc * 128 + n0 + j * 8 + (lane & 3) * 2;
        float bx = b3[col], by = b3[col + 1];
        #pragma unroll
        for (int i = 0; i < 2; i++) {
            #pragma unroll
            for (int half = 0; half < 2; half++) {
                int grow = row0 + m0 + i * 16 + (lane >> 2) + half * 8;
                if (grow < Bc) {
                    float2 o;
                    o.x = tanhf(acc[i][j][half * 2 + 0] + bx);
                    o.y = tanhf(acc[i][j][half * 2 + 1] + by);
                    *(float2*)(out + (size_t)grow * 256 + col) = o;
                }
            }
        }
    }
}

// ---------------- launch ------------------------------------------------------
extern "C" void kernel_launch(void* const* d_in, const int* in_sizes, int n_in,
                              void* d_out, int out_size) {
    const float* x     = (const float*)d_in[0];
    const float* qp    = (const float*)d_in[1];
    const float* fc1_w = (const float*)d_in[2];
    // d_in[3] = fc1_b (cancels in bn1), d_in[7] = fc2_b (cancels in bn2)
    const float* bn1_g = (const float*)d_in[4];
    const float* bn1_b = (const float*)d_in[5];
    const float* fc2_w = (const float*)d_in[6];
    const float* bn2_g = (const float*)d_in[8];
    const float* bn2_b = (const float*)d_in[9];
    const float* fc3_w = (const float*)d_in[10];
    const float* fc3_b = (const float*)d_in[11];
    float* out = (float*)d_out;

    int Bc = in_sizes[0] / 4;
    if (Bc > BMAX) Bc = BMAX;
    float binv = 1.0f / (float)Bc;

    const int SMEM = 2 * 128 * SA * (int)sizeof(float);  // 135168 B
    cudaFuncSetAttribute(k_fc2, cudaFuncAttributeMaxDynamicSharedMemorySize, SMEM);
    cudaFuncSetAttribute(k_fc3, cudaFuncAttributeMaxDynamicSharedMemorySize, SMEM);

    k_zero<<<1, 256>>>();
    k_sim<<<(Bc + 255) / 256, 256>>>(x, qp, Bc);
    k_bn1<<<1, 128>>>(fc1_w, bn1_g, bn1_b, binv);

    dim3 gfc((Bc + 127) / 128, 2);
    k_fc2<<<gfc, 512, SMEM>>>(fc1_w, fc2_w, Bc);
    k_bn2<<<1, 256>>>(bn2_g, bn2_b, binv);
    k_fc3<<<gfc, 512, SMEM>>>(fc3_w, fc3_b, out, Bc);
}

// round 4
// speedup vs baseline: 1.8841x; 1.0229x over previous
#include <cuda_runtime.h>
#include <cuda_fp16.h>
#include <math.h>
#include <stdint.h>

#define BMAX 65536
#define BN_EPS 1e-5f
#define PAD 136   // halves per tile row: 272B = 17*16B (odd) -> ldmatrix conflict-free

// ---------------- scratch (static device globals) -----------------------------
static __device__ float g_q[BMAX * 4];
static __device__ float g_h2[(size_t)BMAX * 256];
static __device__ float g_sumz[4];
static __device__ float g_sumzz[16];
static __device__ float g_sum2[256];
static __device__ float g_sumsq2[256];
static __device__ float g_sc1[128], g_sh1[128];
static __device__ float g_sc2[256], g_sh2[256];

// ---------------- PTX helpers --------------------------------------------------
__device__ __forceinline__ uint32_t smem_u32(const void* p) {
    uint32_t a;
    asm("{ .reg .u64 t; cvta.to.shared.u64 t, %1; cvt.u32.u64 %0, t; }" : "=r"(a) : "l"(p));
    return a;
}
__device__ __forceinline__ void ldmx4(uint32_t& d0, uint32_t& d1, uint32_t& d2, uint32_t& d3,
                                      uint32_t addr) {
    asm volatile("ldmatrix.sync.aligned.m8n8.x4.shared.b16 {%0,%1,%2,%3}, [%4];"
                 : "=r"(d0), "=r"(d1), "=r"(d2), "=r"(d3) : "r"(addr));
}
__device__ __forceinline__ void mma_f16(float* c, const uint32_t* a, const uint32_t* b) {
    asm volatile(
        "mma.sync.aligned.m16n8k16.row.col.f32.f16.f16.f32 "
        "{%0,%1,%2,%3}, {%4,%5,%6,%7}, {%8,%9}, {%0,%1,%2,%3};"
        : "+f"(c[0]), "+f"(c[1]), "+f"(c[2]), "+f"(c[3])
        : "r"(a[0]), "r"(a[1]), "r"(a[2]), "r"(a[3]), "r"(b[0]), "r"(b[1]));
}
__device__ __forceinline__ uint32_t pack_half2(float x, float y) {
    __half2 h = __floats2half2_rn(x, y);
    return *(uint32_t*)&h;
}

// ---------------- zero accumulators ------------------------------------------
__global__ void k_zero() {
    int t = threadIdx.x;
    if (t < 4)  g_sumz[t] = 0.f;
    if (t < 16) g_sumzz[t] = 0.f;
    if (t < 256) { g_sum2[t] = 0.f; g_sumsq2[t] = 0.f; }
}

// ---------------- quantum simulator + q statistics ----------------------------
__global__ void k_sim(const float* __restrict__ x, const float* __restrict__ qp, int Bc) {
    int t = blockIdx.x * blockDim.x + threadIdx.x;
    float z[4] = {0.f, 0.f, 0.f, 0.f};
    if (t < Bc) {
        float xr[4];
        #pragma unroll
        for (int i = 0; i < 4; i++) xr[i] = x[t * 4 + i];
        float re[16], im[16];
        #pragma unroll
        for (int i = 0; i < 16; i++) { re[i] = 0.f; im[i] = 0.f; }
        re[0] = 1.f;
        #pragma unroll
        for (int d = 0; d < 3; d++) {
            #pragma unroll
            for (int i = 0; i < 4; i++) {
                float s, c;
                sincosf(0.5f * (xr[i] + qp[d * 8 + i]), &s, &c);
                int m = 1 << (3 - i);
                #pragma unroll
                for (int idx = 0; idx < 16; idx++) {
                    if ((idx & m) == 0) {
                        int p = idx | m;
                        float a0r = re[idx], a0i = im[idx];
                        float a1r = re[p],  a1i = im[p];
                        re[idx] = c * a0r - s * a1r;  im[idx] = c * a0i - s * a1i;
                        re[p]   = s * a0r + c * a1r;  im[p]   = s * a0i + c * a1i;
                    }
                }
            }
            #pragma unroll
            for (int i = 0; i < 4; i++) {
                int cm = 1 << (3 - i);
                int tm = 1 << (3 - ((i + 1) & 3));
                #pragma unroll
                for (int idx = 0; idx < 16; idx++) {
                    if ((idx & cm) && !(idx & tm)) {
                        int p = idx | tm;
                        float tr = re[idx]; re[idx] = re[p]; re[p] = tr;
                        float ti = im[idx]; im[idx] = im[p]; im[p] = ti;
                    }
                }
            }
            #pragma unroll
            for (int i = 0; i < 4; i++) {
                float s, c;
                sincosf(0.5f * qp[d * 8 + 4 + i], &s, &c);
                int m = 1 << (3 - i);
                #pragma unroll
                for (int idx = 0; idx < 16; idx++) {
                    float pi = (idx & m) ? s : -s;
                    float r0 = re[idx], i0 = im[idx];
                    re[idx] = r0 * c - i0 * pi;
                    im[idx] = i0 * c + r0 * pi;
                }
            }
        }
        #pragma unroll
        for (int i = 0; i < 4; i++) {
            int m = 1 << (3 - i);
            float acc = 0.f;
            #pragma unroll
            for (int idx = 0; idx < 16; idx++) {
                float p = re[idx] * re[idx] + im[idx] * im[idx];
                acc += (idx & m) ? -p : p;
            }
            z[i] = acc;
        }
        *(float4*)(g_q + (size_t)t * 4) = make_float4(z[0], z[1], z[2], z[3]);
    }
    float vals[20];
    #pragma unroll
    for (int a = 0; a < 4; a++) vals[a] = z[a];
    #pragma unroll
    for (int a = 0; a < 4; a++)
        #pragma unroll
        for (int b = 0; b < 4; b++) vals[4 + a * 4 + b] = z[a] * z[b];
    #pragma unroll
    for (int v = 0; v < 20; v++) {
        #pragma unroll
        for (int off = 16; off > 0; off >>= 1)
            vals[v] += __shfl_xor_sync(0xffffffffu, vals[v], off);
    }
    if ((threadIdx.x & 31) == 0) {
        #pragma unroll
        for (int a = 0; a < 4; a++) atomicAdd(&g_sumz[a], vals[a]);
        #pragma unroll
        for (int v = 0; v < 16; v++) atomicAdd(&g_sumzz[v], vals[4 + v]);
    }
}

// ---------------- bn1 params (analytic) ---------------------------------------
__global__ void k_bn1(const float* __restrict__ w1, const float* __restrict__ g,
                      const float* __restrict__ b, float binv) {
    int j = threadIdx.x;
    float mu[4], C[16];
    #pragma unroll
    for (int a = 0; a < 4; a++) mu[a] = g_sumz[a] * binv;
    #pragma unroll
    for (int a = 0; a < 4; a++)
        #pragma unroll
        for (int c = 0; c < 4; c++)
            C[a * 4 + c] = g_sumzz[a * 4 + c] * binv - mu[a] * mu[c];
    float w[4];
    #pragma unroll
    for (int a = 0; a < 4; a++) w[a] = w1[j * 4 + a];
    float m0 = 0.f, v = 0.f;
    #pragma unroll
    for (int a = 0; a < 4; a++) {
        m0 += w[a] * mu[a];
        #pragma unroll
        for (int c = 0; c < 4; c++) v += w[a] * w[c] * C[a * 4 + c];
    }
    float sc = g[j] * rsqrtf(v + BN_EPS);
    g_sc1[j] = sc;
    g_sh1[j] = b[j] - sc * m0;
}

__global__ void k_bn2(const float* __restrict__ g, const float* __restrict__ b, float binv) {
    int j = threadIdx.x;
    float mean = g_sum2[j] * binv;
    float var  = g_sumsq2[j] * binv - mean * mean;
    float sc = g[j] * rsqrtf(var + BN_EPS);
    g_sc2[j] = sc;
    g_sh2[j] = b[j] - sc * mean;
}

// ---------------- fc2: fp16 mma + ldmatrix, fused fc1/bn1/relu + bn2 stats ----
__global__ void __launch_bounds__(512, 1)
k_fc2(const float* __restrict__ w1, const float* __restrict__ w2, int Bc) {
    extern __shared__ char dyn[];
    __half* As = (__half*)dyn;               // [128][PAD]
    __half* Bs = As + 128 * PAD;             // [128][PAD]
    __shared__ float qs[512], w1s[512], sc1s[128], sh1s[128];
    __shared__ float redS[16 * 32], redQ[16 * 32];

    int tid = threadIdx.x;
    int row0 = blockIdx.x * 128;
    int bc = blockIdx.y;

    {
        w1s[tid] = w1[tid];                  // [f][a] layout, direct copy (512 vals)
        if (tid < 128) {
            int r = row0 + tid;
            float4 q = (r < Bc) ? *(const float4*)(g_q + (size_t)r * 4)
                                : make_float4(0.f, 0.f, 0.f, 0.f);
            *(float4*)(qs + tid * 4) = q;
            sc1s[tid] = g_sc1[tid];
            sh1s[tid] = g_sh1[tid];
        }
    }
    __syncthreads();

    // A-stage: h1r from q on the fly -> half tile
    #pragma unroll
    for (int i = 0; i < 8; i++) {
        int idx = tid + i * 512;
        int r = idx >> 4, g8 = (idx & 15) << 3;
        if (i >= 4 && r >= 128) break;       // idx < 2048 always; (128*16 = 2048)
        bool valid = (row0 + r < Bc);
        float4 qv = *(const float4*)(qs + r * 4);
        uint32_t pk[4];
        #pragma unroll
        for (int p = 0; p < 4; p++) {
            int f0 = g8 + 2 * p, f1 = f0 + 1;
            float d0 = qv.x * w1s[f0 * 4] + qv.y * w1s[f0 * 4 + 1]
                     + qv.z * w1s[f0 * 4 + 2] + qv.w * w1s[f0 * 4 + 3];
            float d1 = qv.x * w1s[f1 * 4] + qv.y * w1s[f1 * 4 + 1]
                     + qv.z * w1s[f1 * 4 + 2] + qv.w * w1s[f1 * 4 + 3];
            float v0 = valid ? fmaxf(fmaf(sc1s[f0], d0, sh1s[f0]), 0.f) : 0.f;
            float v1 = valid ? fmaxf(fmaf(sc1s[f1], d1, sh1s[f1]), 0.f) : 0.f;
            pk[p] = pack_half2(v0, v1);
        }
        *(uint4*)(As + r * PAD + g8) = make_uint4(pk[0], pk[1], pk[2], pk[3]);
        if (i == 3) break;                   // 512*4 = 2048 covers the tile
    }
    // B-stage: w2 [256][128] row-major = n-major operand
    #pragma unroll
    for (int i = 0; i < 4; i++) {
        int idx = tid + i * 512;
        int n = idx >> 4, g8 = (idx & 15) << 3;
        const float* src = w2 + (size_t)(bc * 128 + n) * 128 + g8;
        float4 a = *(const float4*)src;
        float4 b = *(const float4*)(src + 4);
        *(uint4*)(Bs + n * PAD + g8) = make_uint4(
            pack_half2(a.x, a.y), pack_half2(a.z, a.w),
            pack_half2(b.x, b.y), pack_half2(b.z, b.w));
    }
    __syncthreads();

    int lane = tid & 31, wid = tid >> 5;
    int wr = wid >> 2, wc = wid & 3;
    int m0 = wr * 32, n0 = wc * 32;
    int lrow = lane & 7, mat = lane >> 3;
    int rb = (mat & 1) * 8, kb = (mat >> 1) * 8;

    uint32_t aAddr0 = smem_u32(As + (m0 + rb + lrow) * PAD + kb);
    uint32_t aAddr1 = smem_u32(As + (m0 + 16 + rb + lrow) * PAD + kb);
    uint32_t bAddr0 = smem_u32(Bs + (n0 + rb + lrow) * PAD + kb);
    uint32_t bAddr1 = smem_u32(Bs + (n0 + 16 + rb + lrow) * PAD + kb);

    float acc[2][4][4];
    #pragma unroll
    for (int i = 0; i < 2; i++)
        #pragma unroll
        for (int j = 0; j < 4; j++)
            #pragma unroll
            for (int p = 0; p < 4; p++) acc[i][j][p] = 0.f;

    #pragma unroll
    for (int s = 0; s < 8; s++) {
        uint32_t a[2][4], b[4][2];
        ldmx4(a[0][0], a[0][1], a[0][2], a[0][3], aAddr0 + s * 32);
        ldmx4(a[1][0], a[1][1], a[1][2], a[1][3], aAddr1 + s * 32);
        ldmx4(b[0][0], b[1][0], b[0][1], b[1][1], bAddr0 + s * 32);
        ldmx4(b[2][0], b[3][0], b[2][1], b[3][1], bAddr1 + s * 32);
        #pragma unroll
        for (int i = 0; i < 2; i++)
            #pragma unroll
            for (int j = 0; j < 4; j++)
                mma_f16(acc[i][j], a[i], b[j]);
    }

    // epilogue: store h2 + fused column stats (same C layout as R2)
    float cs[4][2], cq[4][2];
    #pragma unroll
    for (int j = 0; j < 4; j++) { cs[j][0] = cs[j][1] = cq[j][0] = cq[j][1] = 0.f; }

    #pragma unroll
    for (int i = 0; i < 2; i++) {
        #pragma unroll
        for (int half = 0; half < 2; half++) {
            int grow = row0 + m0 + i * 16 + (lane >> 2) + half * 8;
            #pragma unroll
            for (int j = 0; j < 4; j++) {
                float v0 = acc[i][j][half * 2 + 0];
                float v1 = acc[i][j][half * 2 + 1];
                if (grow < Bc) {
                    *(float2*)(g_h2 + (size_t)grow * 256 + bc * 128 + n0 + j * 8 + (lane & 3) * 2)
                        = make_float2(v0, v1);
                }
                cs[j][0] += v0; cs[j][1] += v1;
                cq[j][0] += v0 * v0; cq[j][1] += v1 * v1;
            }
        }
    }
    #pragma unroll
    for (int j = 0; j < 4; j++)
        #pragma unroll
        for (int p = 0; p < 2; p++) {
            #pragma unroll
            for (int off = 4; off < 32; off <<= 1) {
                cs[j][p] += __shfl_xor_sync(0xffffffffu, cs[j][p], off);
                cq[j][p] += __shfl_xor_sync(0xffffffffu, cq[j][p], off);
            }
        }
    if (lane < 4) {
        #pragma unroll
        for (int j = 0; j < 4; j++)
            #pragma unroll
            for (int p = 0; p < 2; p++) {
                int c32 = j * 8 + lane * 2 + p;
                redS[wid * 32 + c32] = cs[j][p];
                redQ[wid * 32 + c32] = cq[j][p];
            }
    }
    __syncthreads();
    if (tid < 128) {
        int wcg = tid >> 5, c32 = tid & 31;
        float s = 0.f, q = 0.f;
        #pragma unroll
        for (int w = 0; w < 4; w++) {
            s += redS[(w * 4 + wcg) * 32 + c32];
            q += redQ[(w * 4 + wcg) * 32 + c32];
        }
        atomicAdd(&g_sum2[bc * 128 + tid], s);
        atomicAdd(&g_sumsq2[bc * 128 + tid], q);
    }
}

// ---------------- fc3: fp16 mma + ldmatrix (K=256), bn2+relu in, tanh out -----
__global__ void __launch_bounds__(512, 1)
k_fc3(const float* __restrict__ w3, const float* __restrict__ b3,
      float* __restrict__ out, int Bc) {
    extern __shared__ char dyn[];
    __half* As = (__half*)dyn;
    __half* Bs = As + 128 * PAD;
    __shared__ float sc2s[256], sh2s[256];

    int tid = threadIdx.x;
    if (tid < 256) { sc2s[tid] = g_sc2[tid]; sh2s[tid] = g_sh2[tid]; }

    int row0 = blockIdx.x * 128;
    int bc = blockIdx.y;
    int lane = tid & 31, wid = tid >> 5;
    int wr = wid >> 2, wc = wid & 3;
    int m0 = wr * 32, n0 = wc * 32;
    int lrow = lane & 7, mat = lane >> 3;
    int rb = (mat & 1) * 8, kb = (mat >> 1) * 8;

    uint32_t aAddr0 = smem_u32(As + (m0 + rb + lrow) * PAD + kb);
    uint32_t aAddr1 = smem_u32(As + (m0 + 16 + rb + lrow) * PAD + kb);
    uint32_t bAddr0 = smem_u32(Bs + (n0 + rb + lrow) * PAD + kb);
    uint32_t bAddr1 = smem_u32(Bs + (n0 + 16 + rb + lrow) * PAD + kb);

    float acc[2][4][4];
    #pragma unroll
    for (int i = 0; i < 2; i++)
        #pragma unroll
        for (int j = 0; j < 4; j++)
            #pragma unroll
            for (int p = 0; p < 4; p++) acc[i][j][p] = 0.f;

    for (int ck = 0; ck < 2; ck++) {
        __syncthreads();   // first iter: covers sc2s init; later: protects tiles
        // A-stage: bn2 + relu on load -> half
        #pragma unroll
        for (int i = 0; i < 4; i++) {
            int idx = tid + i * 512;
            int r = idx >> 4, g8 = (idx & 15) << 3;
            int grow = row0 + r;
            uint32_t pk[4];
            if (grow < Bc) {
                const float* src = g_h2 + (size_t)grow * 256 + ck * 128 + g8;
                float4 ha = *(const float4*)src;
                float4 hb = *(const float4*)(src + 4);
                float v[8] = {ha.x, ha.y, ha.z, ha.w, hb.x, hb.y, hb.z, hb.w};
                #pragma unroll
                for (int e = 0; e < 8; e++) {
                    int f = ck * 128 + g8 + e;
                    v[e] = fmaxf(fmaf(v[e], sc2s[f], sh2s[f]), 0.f);
                }
                pk[0] = pack_half2(v[0], v[1]); pk[1] = pack_half2(v[2], v[3]);
                pk[2] = pack_half2(v[4], v[5]); pk[3] = pack_half2(v[6], v[7]);
            } else {
                pk[0] = pk[1] = pk[2] = pk[3] = 0u;
            }
            *(uint4*)(As + r * PAD + g8) = make_uint4(pk[0], pk[1], pk[2], pk[3]);
        }
        // B-stage: w3 [256][256] row-major
        #pragma unroll
        for (int i = 0; i < 4; i++) {
            int idx = tid + i * 512;
            int n = idx >> 4, g8 = (idx & 15) << 3;
            const float* src = w3 + (size_t)(bc * 128 + n) * 256 + ck * 128 + g8;
            float4 a = *(const float4*)src;
            float4 b = *(const float4*)(src + 4);
            *(uint4*)(Bs + n * PAD + g8) = make_uint4(
                pack_half2(a.x, a.y), pack_half2(a.z, a.w),
                pack_half2(b.x, b.y), pack_half2(b.z, b.w));
        }
        __syncthreads();

        #pragma unroll
        for (int s = 0; s < 8; s++) {
            uint32_t a[2][4], b[4][2];
            ldmx4(a[0][0], a[0][1], a[0][2], a[0][3], aAddr0 + s * 32);
            ldmx4(a[1][0], a[1][1], a[1][2], a[1][3], aAddr1 + s * 32);
            ldmx4(b[0][0], b[1][0], b[0][1], b[1][1], bAddr0 + s * 32);
            ldmx4(b[2][0], b[3][0], b[2][1], b[3][1], bAddr1 + s * 32);
            #pragma unroll
            for (int i = 0; i < 2; i++)
                #pragma unroll
                for (int j = 0; j < 4; j++)
                    mma_f16(acc[i][j], a[i], b[j]);
        }
    }

    // epilogue: +bias, tanh, float2 stores
    #pragma unroll
    for (int j = 0; j < 4; j++) {
        int col = bc * 128 + n0 + j * 8 + (lane & 3) * 2;
        float bx = b3[col], by = b3[col + 1];
        #pragma unroll
        for (int i = 0; i < 2; i++) {
            #pragma unroll
            for (int half = 0; half < 2; half++) {
                int grow = row0 + m0 + i * 16 + (lane >> 2) + half * 8;
                if (grow < Bc) {
                    float2 o;
                    o.x = tanhf(acc[i][j][half * 2 + 0] + bx);
                    o.y = tanhf(acc[i][j][half * 2 + 1] + by);
                    *(float2*)(out + (size_t)grow * 256 + col) = o;
                }
            }
        }
    }
}

// ---------------- launch ------------------------------------------------------
extern "C" void kernel_launch(void* const* d_in, const int* in_sizes, int n_in,
                              void* d_out, int out_size) {
    const float* x     = (const float*)d_in[0];
    const float* qp    = (const float*)d_in[1];
    const float* fc1_w = (const float*)d_in[2];
    // d_in[3] = fc1_b (cancels in bn1), d_in[7] = fc2_b (cancels in bn2)
    const float* bn1_g = (const float*)d_in[4];
    const float* bn1_b = (const float*)d_in[5];
    const float* fc2_w = (const float*)d_in[6];
    const float* bn2_g = (const float*)d_in[8];
    const float* bn2_b = (const float*)d_in[9];
    const float* fc3_w = (const float*)d_in[10];
    const float* fc3_b = (const float*)d_in[11];
    float* out = (float*)d_out;

    int Bc = in_sizes[0] / 4;
    if (Bc > BMAX) Bc = BMAX;
    float binv = 1.0f / (float)Bc;

    const int SMEM = 2 * 128 * PAD * (int)sizeof(__half);  // 69632 B
    cudaFuncSetAttribute(k_fc2, cudaFuncAttributeMaxDynamicSharedMemorySize, SMEM);
    cudaFuncSetAttribute(k_fc3, cudaFuncAttributeMaxDynamicSharedMemorySize, SMEM);

    k_zero<<<1, 256>>>();
    k_sim<<<(Bc + 255) / 256, 256>>>(x, qp, Bc);
    k_bn1<<<1, 128>>>(fc1_w, bn1_g, bn1_b, binv);

    dim3 gfc((Bc + 127) / 128, 2);
    k_fc2<<<gfc, 512, SMEM>>>(fc1_w, fc2_w, Bc);
    k_bn2<<<1, 256>>>(bn2_g, bn2_b, binv);
    k_fc3<<<gfc, 512, SMEM>>>(fc3_w, fc3_b, out, Bc);
}

// round 5
// speedup vs baseline: 2.1323x; 1.1317x over previous
#include <cuda_runtime.h>
#include <cuda_fp16.h>
#include <math.h>
#include <stdint.h>

#define BMAX 65536
#define BN_EPS 1e-5f
#define PAD 136   // halves per tile row: 272B = 17*16B -> ldmatrix conflict-free

// ---------------- scratch (static device globals) -----------------------------
static __device__ float  g_q[BMAX * 4];
static __device__ __half g_h2h[(size_t)BMAX * 256];    // 32 MB, L2-resident
static __device__ float g_sumz[4];
static __device__ float g_sumzz[16];
static __device__ float g_sum2[256];
static __device__ float g_sumsq2[256];

// ---------------- PTX helpers --------------------------------------------------
__device__ __forceinline__ uint32_t smem_u32(const void* p) {
    uint32_t a;
    asm("{ .reg .u64 t; cvta.to.shared.u64 t, %1; cvt.u32.u64 %0, t; }" : "=r"(a) : "l"(p));
    return a;
}
__device__ __forceinline__ void ldmx4(uint32_t& d0, uint32_t& d1, uint32_t& d2, uint32_t& d3,
                                      uint32_t addr) {
    asm volatile("ldmatrix.sync.aligned.m8n8.x4.shared.b16 {%0,%1,%2,%3}, [%4];"
                 : "=r"(d0), "=r"(d1), "=r"(d2), "=r"(d3) : "r"(addr));
}
__device__ __forceinline__ void mma_f16(float* c, const uint32_t* a, const uint32_t* b) {
    asm volatile(
        "mma.sync.aligned.m16n8k16.row.col.f32.f16.f16.f32 "
        "{%0,%1,%2,%3}, {%4,%5,%6,%7}, {%8,%9}, {%0,%1,%2,%3};"
        : "+f"(c[0]), "+f"(c[1]), "+f"(c[2]), "+f"(c[3])
        : "r"(a[0]), "r"(a[1]), "r"(a[2]), "r"(a[3]), "r"(b[0]), "r"(b[1]));
}
__device__ __forceinline__ uint32_t pack_half2(float x, float y) {
    __half2 h = __floats2half2_rn(x, y);
    return *(uint32_t*)&h;
}

// ---------------- zero accumulators ------------------------------------------
__global__ void k_zero() {
    int t = threadIdx.x;
    if (t < 4)  g_sumz[t] = 0.f;
    if (t < 16) g_sumzz[t] = 0.f;
    if (t < 256) { g_sum2[t] = 0.f; g_sumsq2[t] = 0.f; }
}

// ---------------- quantum simulator + q statistics ----------------------------
__global__ void k_sim(const float* __restrict__ x, const float* __restrict__ qp, int Bc) {
    int t = blockIdx.x * blockDim.x + threadIdx.x;
    float z[4] = {0.f, 0.f, 0.f, 0.f};
    if (t < Bc) {
        float xr[4];
        #pragma unroll
        for (int i = 0; i < 4; i++) xr[i] = x[t * 4 + i];
        float re[16], im[16];
        #pragma unroll
        for (int i = 0; i < 16; i++) { re[i] = 0.f; im[i] = 0.f; }
        re[0] = 1.f;
        #pragma unroll
        for (int d = 0; d < 3; d++) {
            #pragma unroll
            for (int i = 0; i < 4; i++) {
                float s, c;
                sincosf(0.5f * (xr[i] + qp[d * 8 + i]), &s, &c);
                int m = 1 << (3 - i);
                #pragma unroll
                for (int idx = 0; idx < 16; idx++) {
                    if ((idx & m) == 0) {
                        int p = idx | m;
                        float a0r = re[idx], a0i = im[idx];
                        float a1r = re[p],  a1i = im[p];
                        re[idx] = c * a0r - s * a1r;  im[idx] = c * a0i - s * a1i;
                        re[p]   = s * a0r + c * a1r;  im[p]   = s * a0i + c * a1i;
                    }
                }
            }
            #pragma unroll
            for (int i = 0; i < 4; i++) {
                int cm = 1 << (3 - i);
                int tm = 1 << (3 - ((i + 1) & 3));
                #pragma unroll
                for (int idx = 0; idx < 16; idx++) {
                    if ((idx & cm) && !(idx & tm)) {
                        int p = idx | tm;
                        float tr = re[idx]; re[idx] = re[p]; re[p] = tr;
                        float ti = im[idx]; im[idx] = im[p]; im[p] = ti;
                    }
                }
            }
            #pragma unroll
            for (int i = 0; i < 4; i++) {
                float s, c;
                sincosf(0.5f * qp[d * 8 + 4 + i], &s, &c);
                int m = 1 << (3 - i);
                #pragma unroll
                for (int idx = 0; idx < 16; idx++) {
                    float pi = (idx & m) ? s : -s;
                    float r0 = re[idx], i0 = im[idx];
                    re[idx] = r0 * c - i0 * pi;
                    im[idx] = i0 * c + r0 * pi;
                }
            }
        }
        #pragma unroll
        for (int i = 0; i < 4; i++) {
            int m = 1 << (3 - i);
            float acc = 0.f;
            #pragma unroll
            for (int idx = 0; idx < 16; idx++) {
                float p = re[idx] * re[idx] + im[idx] * im[idx];
                acc += (idx & m) ? -p : p;
            }
            z[i] = acc;
        }
        *(float4*)(g_q + (size_t)t * 4) = make_float4(z[0], z[1], z[2], z[3]);
    }
    float vals[20];
    #pragma unroll
    for (int a = 0; a < 4; a++) vals[a] = z[a];
    #pragma unroll
    for (int a = 0; a < 4; a++)
        #pragma unroll
        for (int b = 0; b < 4; b++) vals[4 + a * 4 + b] = z[a] * z[b];
    #pragma unroll
    for (int v = 0; v < 20; v++) {
        #pragma unroll
        for (int off = 16; off > 0; off >>= 1)
            vals[v] += __shfl_xor_sync(0xffffffffu, vals[v], off);
    }
    if ((threadIdx.x & 31) == 0) {
        #pragma unroll
        for (int a = 0; a < 4; a++) atomicAdd(&g_sumz[a], vals[a]);
        #pragma unroll
        for (int v = 0; v < 16; v++) atomicAdd(&g_sumzz[v], vals[4 + v]);
    }
}

// ---------------- fc2: fp16 mma, 256 thr, 2 CTA/SM, fused bn1 + bn2 stats -----
__global__ void __launch_bounds__(256, 2)
k_fc2(const float* __restrict__ w1, const float* __restrict__ w2,
      const float* __restrict__ bn1g, const float* __restrict__ bn1b,
      int Bc, float binv) {
    extern __shared__ char dynsm[];
    __half* As = (__half*)dynsm;             // [128][PAD]
    __half* Bs = As + 128 * PAD;             // [128][PAD]
    __shared__ float qs[512], w1s[512], sc1s[128], sh1s[128];
    __shared__ float redS[8 * 32], redQ[8 * 32];

    int tid = threadIdx.x;
    int row0 = blockIdx.x * 128;
    int bc = blockIdx.y;

    // inline bn1 params (analytic; redundant per block, trivial)
    if (tid < 128) {
        int j = tid;
        float mu[4], C[16];
        #pragma unroll
        for (int a = 0; a < 4; a++) mu[a] = g_sumz[a] * binv;
        #pragma unroll
        for (int a = 0; a < 4; a++)
            #pragma unroll
            for (int c = 0; c < 4; c++)
                C[a * 4 + c] = g_sumzz[a * 4 + c] * binv - mu[a] * mu[c];
        float w[4];
        #pragma unroll
        for (int a = 0; a < 4; a++) w[a] = w1[j * 4 + a];
        float m0v = 0.f, v = 0.f;
        #pragma unroll
        for (int a = 0; a < 4; a++) {
            m0v += w[a] * mu[a];
            #pragma unroll
            for (int c = 0; c < 4; c++) v += w[a] * w[c] * C[a * 4 + c];
        }
        float sc = bn1g[j] * rsqrtf(v + BN_EPS);
        sc1s[j] = sc;
        sh1s[j] = bn1b[j] - sc * m0v;
        // stage q rows
        int r = row0 + j;
        float4 q = (r < Bc) ? *(const float4*)(g_q + (size_t)r * 4)
                            : make_float4(0.f, 0.f, 0.f, 0.f);
        *(float4*)(qs + j * 4) = q;
    }
    w1s[tid] = w1[tid];
    w1s[tid + 256] = w1[tid + 256];
    __syncthreads();

    // A-stage: h1r from q on the fly -> half tile
    #pragma unroll
    for (int i = 0; i < 8; i++) {
        int idx = tid + i * 256;
        int r = idx >> 4, g8 = (idx & 15) << 3;
        bool valid = (row0 + r < Bc);
        float4 qv = *(const float4*)(qs + r * 4);
        uint32_t pk[4];
        #pragma unroll
        for (int p = 0; p < 4; p++) {
            int f0 = g8 + 2 * p, f1 = f0 + 1;
            float d0 = qv.x * w1s[f0 * 4] + qv.y * w1s[f0 * 4 + 1]
                     + qv.z * w1s[f0 * 4 + 2] + qv.w * w1s[f0 * 4 + 3];
            float d1 = qv.x * w1s[f1 * 4] + qv.y * w1s[f1 * 4 + 1]
                     + qv.z * w1s[f1 * 4 + 2] + qv.w * w1s[f1 * 4 + 3];
            float v0 = valid ? fmaxf(fmaf(sc1s[f0], d0, sh1s[f0]), 0.f) : 0.f;
            float v1 = valid ? fmaxf(fmaf(sc1s[f1], d1, sh1s[f1]), 0.f) : 0.f;
            pk[p] = pack_half2(v0, v1);
        }
        *(uint4*)(As + r * PAD + g8) = make_uint4(pk[0], pk[1], pk[2], pk[3]);
    }
    // B-stage: w2 [256][128] row-major = n-major operand
    #pragma unroll
    for (int i = 0; i < 8; i++) {
        int idx = tid + i * 256;
        int n = idx >> 4, g8 = (idx & 15) << 3;
        const float* src = w2 + (size_t)(bc * 128 + n) * 128 + g8;
        float4 a = *(const float4*)src;
        float4 b = *(const float4*)(src + 4);
        *(uint4*)(Bs + n * PAD + g8) = make_uint4(
            pack_half2(a.x, a.y), pack_half2(a.z, a.w),
            pack_half2(b.x, b.y), pack_half2(b.z, b.w));
    }
    __syncthreads();

    int lane = tid & 31, wid = tid >> 5;
    int wr = wid >> 2, wc = wid & 3;
    int m0 = wr * 64, n0 = wc * 32;
    int lrow = lane & 7, mat = lane >> 3;
    int rb = (mat & 1) * 8, kb = (mat >> 1) * 8;

    uint32_t aA[4], bA[2];
    #pragma unroll
    for (int i = 0; i < 4; i++)
        aA[i] = smem_u32(As + (m0 + i * 16 + rb + lrow) * PAD + kb);
    #pragma unroll
    for (int j = 0; j < 2; j++)
        bA[j] = smem_u32(Bs + (n0 + j * 16 + rb + lrow) * PAD + kb);

    float acc[4][4][4];
    #pragma unroll
    for (int i = 0; i < 4; i++)
        #pragma unroll
        for (int j = 0; j < 4; j++)
            #pragma unroll
            for (int p = 0; p < 4; p++) acc[i][j][p] = 0.f;

    #pragma unroll
    for (int s = 0; s < 8; s++) {
        uint32_t a[4][4], b[4][2];
        #pragma unroll
        for (int i = 0; i < 4; i++)
            ldmx4(a[i][0], a[i][1], a[i][2], a[i][3], aA[i] + s * 32);
        #pragma unroll
        for (int j2 = 0; j2 < 2; j2++)
            ldmx4(b[2*j2][0], b[2*j2+1][0], b[2*j2][1], b[2*j2+1][1], bA[j2] + s * 32);
        #pragma unroll
        for (int i = 0; i < 4; i++)
            #pragma unroll
            for (int j = 0; j < 4; j++)
                mma_f16(acc[i][j], a[i], b[j]);
    }

    // epilogue: stats + fp16 h2 via smem staging (tiles are dead after sync)
    __syncthreads();
    __half* stage = As;                       // [128][PAD]
    float cs[4][2], cq[4][2];
    #pragma unroll
    for (int j = 0; j < 4; j++) { cs[j][0] = cs[j][1] = cq[j][0] = cq[j][1] = 0.f; }

    #pragma unroll
    for (int i = 0; i < 4; i++) {
        #pragma unroll
        for (int half = 0; half < 2; half++) {
            int rloc = m0 + i * 16 + (lane >> 2) + half * 8;
            #pragma unroll
            for (int j = 0; j < 4; j++) {
                float v0 = acc[i][j][half * 2 + 0];
                float v1 = acc[i][j][half * 2 + 1];
                int cloc = n0 + j * 8 + (lane & 3) * 2;
                *(uint32_t*)(stage + rloc * PAD + cloc) = pack_half2(v0, v1);
                cs[j][0] += v0; cs[j][1] += v1;
                cq[j][0] += v0 * v0; cq[j][1] += v1 * v1;
            }
        }
    }
    #pragma unroll
    for (int j = 0; j < 4; j++)
        #pragma unroll
        for (int p = 0; p < 2; p++) {
            #pragma unroll
            for (int off = 4; off < 32; off <<= 1) {
                cs[j][p] += __shfl_xor_sync(0xffffffffu, cs[j][p], off);
                cq[j][p] += __shfl_xor_sync(0xffffffffu, cq[j][p], off);
            }
        }
    if (lane < 4) {
        #pragma unroll
        for (int j = 0; j < 4; j++)
            #pragma unroll
            for (int p = 0; p < 2; p++) {
                int c32 = j * 8 + lane * 2 + p;
                redS[wid * 32 + c32] = cs[j][p];
                redQ[wid * 32 + c32] = cq[j][p];
            }
    }
    __syncthreads();

    // coalesced fp16 h2 stores: 128 rows x 256B
    #pragma unroll
    for (int i = 0; i < 8; i++) {
        int idx = tid + i * 256;
        int r = idx >> 4, t = idx & 15;
        if (row0 + r < Bc) {
            uint4 v = *(uint4*)(stage + r * PAD + t * 8);
            *(uint4*)(g_h2h + (size_t)(row0 + r) * 256 + bc * 128 + t * 8) = v;
        }
    }
    if (tid < 128) {
        int wcq = tid >> 5, c32 = tid & 31;
        float s = redS[wcq * 32 + c32] + redS[(4 + wcq) * 32 + c32];
        float q = redQ[wcq * 32 + c32] + redQ[(4 + wcq) * 32 + c32];
        atomicAdd(&g_sum2[bc * 128 + tid], s);
        atomicAdd(&g_sumsq2[bc * 128 + tid], q);
    }
}

// ---------------- fc3: fp16 mma (K=256), fused bn2 params + relu in, tanh out -
__global__ void __launch_bounds__(256, 2)
k_fc3(const float* __restrict__ w3, const float* __restrict__ b3,
      const float* __restrict__ bn2g, const float* __restrict__ bn2b,
      float* __restrict__ out, int Bc, float binv) {
    extern __shared__ char dynsm[];
    __half* As = (__half*)dynsm;
    __half* Bs = As + 128 * PAD;
    __shared__ float sc2s[256], sh2s[256], b3s[128];

    int tid = threadIdx.x;
    int row0 = blockIdx.x * 128;
    int bc = blockIdx.y;

    {   // inline bn2 params (j = tid; 256 cols)
        float mean = g_sum2[tid] * binv;
        float var  = g_sumsq2[tid] * binv - mean * mean;
        float sc = bn2g[tid] * rsqrtf(var + BN_EPS);
        sc2s[tid] = sc;
        sh2s[tid] = bn2b[tid] - sc * mean;
        if (tid < 128) b3s[tid] = b3[bc * 128 + tid];
    }

    int lane = tid & 31, wid = tid >> 5;
    int wr = wid >> 2, wc = wid & 3;
    int m0 = wr * 64, n0 = wc * 32;
    int lrow = lane & 7, mat = lane >> 3;
    int rb = (mat & 1) * 8, kb = (mat >> 1) * 8;

    uint32_t aA[4], bA[2];
    #pragma unroll
    for (int i = 0; i < 4; i++)
        aA[i] = smem_u32(As + (m0 + i * 16 + rb + lrow) * PAD + kb);
    #pragma unroll
    for (int j = 0; j < 2; j++)
        bA[j] = smem_u32(Bs + (n0 + j * 16 + rb + lrow) * PAD + kb);

    float acc[4][4][4];
    #pragma unroll
    for (int i = 0; i < 4; i++)
        #pragma unroll
        for (int j = 0; j < 4; j++)
            #pragma unroll
            for (int p = 0; p < 4; p++) acc[i][j][p] = 0.f;

    for (int ck = 0; ck < 2; ck++) {
        __syncthreads();   // ck=0: sc2s ready; ck=1: all warps done reading tiles
        // A-stage: fp16 h2 load, bn2 + relu, repack
        #pragma unroll
        for (int i = 0; i < 8; i++) {
            int idx = tid + i * 256;
            int r = idx >> 4, t = idx & 15;
            int grow = row0 + r;
            uint32_t pk[4];
            if (grow < Bc) {
                uint4 hv = *(const uint4*)(g_h2h + (size_t)grow * 256 + ck * 128 + t * 8);
                const uint32_t* hw = (const uint32_t*)&hv;
                int f0 = ck * 128 + t * 8;
                #pragma unroll
                for (int p = 0; p < 4; p++) {
                    float2 h = __half22float2(*(const __half2*)&hw[p]);
                    float v0 = fmaxf(fmaf(h.x, sc2s[f0 + 2*p],     sh2s[f0 + 2*p]), 0.f);
                    float v1 = fmaxf(fmaf(h.y, sc2s[f0 + 2*p + 1], sh2s[f0 + 2*p + 1]), 0.f);
                    pk[p] = pack_half2(v0, v1);
                }
            } else {
                pk[0] = pk[1] = pk[2] = pk[3] = 0u;
            }
            *(uint4*)(As + r * PAD + (t << 3)) = make_uint4(pk[0], pk[1], pk[2], pk[3]);
        }
        // B-stage: w3 [256][256] row-major
        #pragma unroll
        for (int i = 0; i < 8; i++) {
            int idx = tid + i * 256;
            int n = idx >> 4, g8 = (idx & 15) << 3;
            const float* src = w3 + (size_t)(bc * 128 + n) * 256 + ck * 128 + g8;
            float4 a = *(const float4*)src;
            float4 b = *(const float4*)(src + 4);
            *(uint4*)(Bs + n * PAD + g8) = make_uint4(
                pack_half2(a.x, a.y), pack_half2(a.z, a.w),
                pack_half2(b.x, b.y), pack_half2(b.z, b.w));
        }
        __syncthreads();

        #pragma unroll
        for (int s = 0; s < 8; s++) {
            uint32_t a[4][4], b[4][2];
            #pragma unroll
            for (int i = 0; i < 4; i++)
                ldmx4(a[i][0], a[i][1], a[i][2], a[i][3], aA[i] + s * 32);
            #pragma unroll
            for (int j2 = 0; j2 < 2; j2++)
                ldmx4(b[2*j2][0], b[2*j2+1][0], b[2*j2][1], b[2*j2+1][1], bA[j2] + s * 32);
            #pragma unroll
            for (int i = 0; i < 4; i++)
                #pragma unroll
                for (int j = 0; j < 4; j++)
                    mma_f16(acc[i][j], a[i], b[j]);
        }
    }

    // epilogue: +bias, tanh, fp32 staging (69632B region = exactly [128][136] f32)
    __syncthreads();
    float* stagef = (float*)dynsm;
    #pragma unroll
    for (int i = 0; i < 4; i++) {
        #pragma unroll
        for (int half = 0; half < 2; half++) {
            int rloc = m0 + i * 16 + (lane >> 2) + half * 8;
            #pragma unroll
            for (int j = 0; j < 4; j++) {
                int cloc = n0 + j * 8 + (lane & 3) * 2;
                float2 o;
                o.x = tanhf(acc[i][j][half * 2 + 0] + b3s[cloc]);
                o.y = tanhf(acc[i][j][half * 2 + 1] + b3s[cloc + 1]);
                *(float2*)(stagef + rloc * 136 + cloc) = o;
            }
        }
    }
    __syncthreads();
    #pragma unroll
    for (int i = 0; i < 16; i++) {
        int idx = tid + i * 256;
        int r = idx >> 5, t = idx & 31;
        if (row0 + r < Bc) {
            float4 v = *(float4*)(stagef + r * 136 + t * 4);
            *(float4*)(out + (size_t)(row0 + r) * 256 + bc * 128 + t * 4) = v;
        }
    }
}

// ---------------- launch ------------------------------------------------------
extern "C" void kernel_launch(void* const* d_in, const int* in_sizes, int n_in,
                              void* d_out, int out_size) {
    const float* x     = (const float*)d_in[0];
    const float* qp    = (const float*)d_in[1];
    const float* fc1_w = (const float*)d_in[2];
    // d_in[3] = fc1_b (cancels in bn1), d_in[7] = fc2_b (cancels in bn2)
    const float* bn1_g = (const float*)d_in[4];
    const float* bn1_b = (const float*)d_in[5];
    const float* fc2_w = (const float*)d_in[6];
    const float* bn2_g = (const float*)d_in[8];
    const float* bn2_b = (const float*)d_in[9];
    const float* fc3_w = (const float*)d_in[10];
    const float* fc3_b = (const float*)d_in[11];
    float* out = (float*)d_out;

    int Bc = in_sizes[0] / 4;
    if (Bc > BMAX) Bc = BMAX;
    float binv = 1.0f / (float)Bc;

    const int SMEM = 2 * 128 * PAD * (int)sizeof(__half);  // 69632 B
    cudaFuncSetAttribute(k_fc2, cudaFuncAttributeMaxDynamicSharedMemorySize, SMEM);
    cudaFuncSetAttribute(k_fc3, cudaFuncAttributeMaxDynamicSharedMemorySize, SMEM);

    k_zero<<<1, 256>>>();
    k_sim<<<(Bc + 255) / 256, 256>>>(x, qp, Bc);

    dim3 gfc((Bc + 127) / 128, 2);
    k_fc2<<<gfc, 256, SMEM>>>(fc1_w, fc2_w, bn1_g, bn1_b, Bc, binv);
    k_fc3<<<gfc, 256, SMEM>>>(fc3_w, fc3_b, bn2_g, bn2_b, out, Bc, binv);
}

// round 6
// speedup vs baseline: 2.6030x; 1.2208x over previous
#include <cuda_runtime.h>
#include <cuda_fp16.h>
#include <math.h>
#include <stdint.h>

#define BMAX 65536
#define BN_EPS 1e-5f
#define PAD 136   // halves per tile row: 272B = 17*16B -> ldmatrix conflict-free

// ---------------- scratch (static device globals) -----------------------------
static __device__ float  g_q[BMAX * 4];
static __device__ __half g_h2h[(size_t)BMAX * 256];    // 32 MB, L2-resident
static __device__ __half g_w2h[256 * 128];
static __device__ __half g_w3h[256 * 256];
static __device__ float g_sumz[4];
static __device__ float g_sumzz[16];
static __device__ float g_sum2[256];
static __device__ float g_sumsq2[256];

// ---------------- PTX helpers --------------------------------------------------
__device__ __forceinline__ uint32_t smem_u32(const void* p) {
    uint32_t a;
    asm("{ .reg .u64 t; cvta.to.shared.u64 t, %1; cvt.u32.u64 %0, t; }" : "=r"(a) : "l"(p));
    return a;
}
__device__ __forceinline__ void ldmx4(uint32_t& d0, uint32_t& d1, uint32_t& d2, uint32_t& d3,
                                      uint32_t addr) {
    asm volatile("ldmatrix.sync.aligned.m8n8.x4.shared.b16 {%0,%1,%2,%3}, [%4];"
                 : "=r"(d0), "=r"(d1), "=r"(d2), "=r"(d3) : "r"(addr));
}
__device__ __forceinline__ void mma_f16(float* c, const uint32_t* a, const uint32_t* b) {
    asm volatile(
        "mma.sync.aligned.m16n8k16.row.col.f32.f16.f16.f32 "
        "{%0,%1,%2,%3}, {%4,%5,%6,%7}, {%8,%9}, {%0,%1,%2,%3};"
        : "+f"(c[0]), "+f"(c[1]), "+f"(c[2]), "+f"(c[3])
        : "r"(a[0]), "r"(a[1]), "r"(a[2]), "r"(a[3]), "r"(b[0]), "r"(b[1]));
}
__device__ __forceinline__ uint32_t pack_half2(float x, float y) {
    __half2 h = __floats2half2_rn(x, y);
    return *(uint32_t*)&h;
}
__device__ __forceinline__ float tanh_fast(float x) {
    float y;
    asm("tanh.approx.f32 %0, %1;" : "=f"(y) : "f"(x));
    return y;
}
__device__ __forceinline__ void cp_async16(uint32_t saddr, const void* gptr) {
    asm volatile("cp.async.ca.shared.global [%0], [%1], 16;" :: "r"(saddr), "l"(gptr));
}
#define CP_COMMIT() asm volatile("cp.async.commit_group;" ::: "memory")
#define CP_WAIT0()  asm volatile("cp.async.wait_group 0;" ::: "memory")

// ---------------- prep: zero accumulators + fp16 weight conversion ------------
__global__ void k_prep(const float* __restrict__ w2, const float* __restrict__ w3) {
    int i = blockIdx.x * blockDim.x + threadIdx.x;
    if (i < 256) {
        if (i < 4)  g_sumz[i] = 0.f;
        if (i < 16) g_sumzz[i] = 0.f;
        g_sum2[i] = 0.f; g_sumsq2[i] = 0.f;
    }
    if (i < 32768) g_w2h[i] = __float2half_rn(w2[i]);
    if (i < 65536) g_w3h[i] = __float2half_rn(w3[i]);
    if (i >= 65536 && i < 98304) {
        int j = i;  // w3 rows 256..: elements 65536..98303
        g_w3h[j] = __float2half_rn(w3[j]);
    }
}

// ---------------- quantum simulator + q statistics ----------------------------
__global__ void k_sim(const float* __restrict__ x, const float* __restrict__ qp, int Bc) {
    int t = blockIdx.x * blockDim.x + threadIdx.x;
    float z[4] = {0.f, 0.f, 0.f, 0.f};
    if (t < Bc) {
        float xr[4];
        #pragma unroll
        for (int i = 0; i < 4; i++) xr[i] = x[t * 4 + i];
        float re[16], im[16];
        #pragma unroll
        for (int i = 0; i < 16; i++) { re[i] = 0.f; im[i] = 0.f; }
        re[0] = 1.f;
        #pragma unroll
        for (int d = 0; d < 3; d++) {
            #pragma unroll
            for (int i = 0; i < 4; i++) {
                float s, c;
                sincosf(0.5f * (xr[i] + qp[d * 8 + i]), &s, &c);
                int m = 1 << (3 - i);
                #pragma unroll
                for (int idx = 0; idx < 16; idx++) {
                    if ((idx & m) == 0) {
                        int p = idx | m;
                        float a0r = re[idx], a0i = im[idx];
                        float a1r = re[p],  a1i = im[p];
                        re[idx] = c * a0r - s * a1r;  im[idx] = c * a0i - s * a1i;
                        re[p]   = s * a0r + c * a1r;  im[p]   = s * a0i + c * a1i;
                    }
                }
            }
            #pragma unroll
            for (int i = 0; i < 4; i++) {
                int cm = 1 << (3 - i);
                int tm = 1 << (3 - ((i + 1) & 3));
                #pragma unroll
                for (int idx = 0; idx < 16; idx++) {
                    if ((idx & cm) && !(idx & tm)) {
                        int p = idx | tm;
                        float tr = re[idx]; re[idx] = re[p]; re[p] = tr;
                        float ti = im[idx]; im[idx] = im[p]; im[p] = ti;
                    }
                }
            }
            #pragma unroll
            for (int i = 0; i < 4; i++) {
                float s, c;
                sincosf(0.5f * qp[d * 8 + 4 + i], &s, &c);
                int m = 1 << (3 - i);
                #pragma unroll
                for (int idx = 0; idx < 16; idx++) {
                    float pi = (idx & m) ? s : -s;
                    float r0 = re[idx], i0 = im[idx];
                    re[idx] = r0 * c - i0 * pi;
                    im[idx] = i0 * c + r0 * pi;
                }
            }
        }
        #pragma unroll
        for (int i = 0; i < 4; i++) {
            int m = 1 << (3 - i);
            float acc = 0.f;
            #pragma unroll
            for (int idx = 0; idx < 16; idx++) {
                float p = re[idx] * re[idx] + im[idx] * im[idx];
                acc += (idx & m) ? -p : p;
            }
            z[i] = acc;
        }
        *(float4*)(g_q + (size_t)t * 4) = make_float4(z[0], z[1], z[2], z[3]);
    }
    float vals[20];
    #pragma unroll
    for (int a = 0; a < 4; a++) vals[a] = z[a];
    #pragma unroll
    for (int a = 0; a < 4; a++)
        #pragma unroll
        for (int b = 0; b < 4; b++) vals[4 + a * 4 + b] = z[a] * z[b];
    #pragma unroll
    for (int v = 0; v < 20; v++) {
        #pragma unroll
        for (int off = 16; off > 0; off >>= 1)
            vals[v] += __shfl_xor_sync(0xffffffffu, vals[v], off);
    }
    if ((threadIdx.x & 31) == 0) {
        #pragma unroll
        for (int a = 0; a < 4; a++) atomicAdd(&g_sumz[a], vals[a]);
        #pragma unroll
        for (int v = 0; v < 16; v++) atomicAdd(&g_sumzz[v], vals[4 + v]);
    }
}

// ---------------- fc2: fp16 mma, cp.async B, fused bn1 + bn2 stats ------------
__global__ void __launch_bounds__(256, 2)
k_fc2(const float* __restrict__ w1,
      const float* __restrict__ bn1g, const float* __restrict__ bn1b,
      int Bc, float binv) {
    extern __shared__ char dynsm[];
    __half* As = (__half*)dynsm;             // [128][PAD]
    __half* Bs = As + 128 * PAD;             // [128][PAD]
    __shared__ float qs[512], w1s[512], sc1s[128], sh1s[128];
    __shared__ float redS[8 * 32], redQ[8 * 32];

    int tid = threadIdx.x;
    int row0 = blockIdx.x * 128;
    int bc = blockIdx.y;

    // B-stage: cp.async fp16 weights (no regs, overlaps everything below)
    #pragma unroll
    for (int i = 0; i < 8; i++) {
        int idx = tid + i * 256;
        int n = idx >> 4, t = idx & 15;
        cp_async16(smem_u32(Bs + n * PAD + t * 8),
                   g_w2h + (size_t)(bc * 128 + n) * 128 + t * 8);
    }
    CP_COMMIT();

    // inline bn1 params (analytic; redundant per block, trivial)
    if (tid < 128) {
        int j = tid;
        float mu[4], C[16];
        #pragma unroll
        for (int a = 0; a < 4; a++) mu[a] = g_sumz[a] * binv;
        #pragma unroll
        for (int a = 0; a < 4; a++)
            #pragma unroll
            for (int c = 0; c < 4; c++)
                C[a * 4 + c] = g_sumzz[a * 4 + c] * binv - mu[a] * mu[c];
        float w[4];
        #pragma unroll
        for (int a = 0; a < 4; a++) w[a] = w1[j * 4 + a];
        float m0v = 0.f, v = 0.f;
        #pragma unroll
        for (int a = 0; a < 4; a++) {
            m0v += w[a] * mu[a];
            #pragma unroll
            for (int c = 0; c < 4; c++) v += w[a] * w[c] * C[a * 4 + c];
        }
        float sc = bn1g[j] * rsqrtf(v + BN_EPS);
        sc1s[j] = sc;
        sh1s[j] = bn1b[j] - sc * m0v;
        int r = row0 + j;
        float4 q = (r < Bc) ? *(const float4*)(g_q + (size_t)r * 4)
                            : make_float4(0.f, 0.f, 0.f, 0.f);
        *(float4*)(qs + j * 4) = q;
    }
    w1s[tid] = w1[tid];
    w1s[tid + 256] = w1[tid + 256];
    __syncthreads();

    // A-stage: h1r from q on the fly -> half tile
    #pragma unroll
    for (int i = 0; i < 8; i++) {
        int idx = tid + i * 256;
        int r = idx >> 4, g8 = (idx & 15) << 3;
        bool valid = (row0 + r < Bc);
        float4 qv = *(const float4*)(qs + r * 4);
        uint32_t pk[4];
        #pragma unroll
        for (int p = 0; p < 4; p++) {
            int f0 = g8 + 2 * p, f1 = f0 + 1;
            float d0 = qv.x * w1s[f0 * 4] + qv.y * w1s[f0 * 4 + 1]
                     + qv.z * w1s[f0 * 4 + 2] + qv.w * w1s[f0 * 4 + 3];
            float d1 = qv.x * w1s[f1 * 4] + qv.y * w1s[f1 * 4 + 1]
                     + qv.z * w1s[f1 * 4 + 2] + qv.w * w1s[f1 * 4 + 3];
            float v0 = valid ? fmaxf(fmaf(sc1s[f0], d0, sh1s[f0]), 0.f) : 0.f;
            float v1 = valid ? fmaxf(fmaf(sc1s[f1], d1, sh1s[f1]), 0.f) : 0.f;
            pk[p] = pack_half2(v0, v1);
        }
        *(uint4*)(As + r * PAD + g8) = make_uint4(pk[0], pk[1], pk[2], pk[3]);
    }
    CP_WAIT0();
    __syncthreads();

    int lane = tid & 31, wid = tid >> 5;
    int wr = wid >> 2, wc = wid & 3;
    int m0 = wr * 64, n0 = wc * 32;
    int lrow = lane & 7, mat = lane >> 3;
    int rb = (mat & 1) * 8, kb = (mat >> 1) * 8;

    uint32_t aA[4], bA[2];
    #pragma unroll
    for (int i = 0; i < 4; i++)
        aA[i] = smem_u32(As + (m0 + i * 16 + rb + lrow) * PAD + kb);
    #pragma unroll
    for (int j = 0; j < 2; j++)
        bA[j] = smem_u32(Bs + (n0 + j * 16 + rb + lrow) * PAD + kb);

    float acc[4][4][4];
    #pragma unroll
    for (int i = 0; i < 4; i++)
        #pragma unroll
        for (int j = 0; j < 4; j++)
            #pragma unroll
            for (int p = 0; p < 4; p++) acc[i][j][p] = 0.f;

    #pragma unroll
    for (int s = 0; s < 8; s++) {
        uint32_t a[4][4], b[4][2];
        #pragma unroll
        for (int i = 0; i < 4; i++)
            ldmx4(a[i][0], a[i][1], a[i][2], a[i][3], aA[i] + s * 32);
        #pragma unroll
        for (int j2 = 0; j2 < 2; j2++)
            ldmx4(b[2*j2][0], b[2*j2+1][0], b[2*j2][1], b[2*j2+1][1], bA[j2] + s * 32);
        #pragma unroll
        for (int i = 0; i < 4; i++)
            #pragma unroll
            for (int j = 0; j < 4; j++)
                mma_f16(acc[i][j], a[i], b[j]);
    }

    // epilogue: stats + fp16 h2 via smem staging (tiles dead after sync)
    __syncthreads();
    __half* stage = As;
    float cs[4][2], cq[4][2];
    #pragma unroll
    for (int j = 0; j < 4; j++) { cs[j][0] = cs[j][1] = cq[j][0] = cq[j][1] = 0.f; }

    #pragma unroll
    for (int i = 0; i < 4; i++) {
        #pragma unroll
        for (int half = 0; half < 2; half++) {
            int rloc = m0 + i * 16 + (lane >> 2) + half * 8;
            #pragma unroll
            for (int j = 0; j < 4; j++) {
                float v0 = acc[i][j][half * 2 + 0];
                float v1 = acc[i][j][half * 2 + 1];
                int cloc = n0 + j * 8 + (lane & 3) * 2;
                *(uint32_t*)(stage + rloc * PAD + cloc) = pack_half2(v0, v1);
                cs[j][0] += v0; cs[j][1] += v1;
                cq[j][0] += v0 * v0; cq[j][1] += v1 * v1;
            }
        }
    }
    #pragma unroll
    for (int j = 0; j < 4; j++)
        #pragma unroll
        for (int p = 0; p < 2; p++) {
            #pragma unroll
            for (int off = 4; off < 32; off <<= 1) {
                cs[j][p] += __shfl_xor_sync(0xffffffffu, cs[j][p], off);
                cq[j][p] += __shfl_xor_sync(0xffffffffu, cq[j][p], off);
            }
        }
    if (lane < 4) {
        #pragma unroll
        for (int j = 0; j < 4; j++)
            #pragma unroll
            for (int p = 0; p < 2; p++) {
                int c32 = j * 8 + lane * 2 + p;
                redS[wid * 32 + c32] = cs[j][p];
                redQ[wid * 32 + c32] = cq[j][p];
            }
    }
    __syncthreads();

    #pragma unroll
    for (int i = 0; i < 8; i++) {
        int idx = tid + i * 256;
        int r = idx >> 4, t = idx & 15;
        if (row0 + r < Bc) {
            uint4 v = *(uint4*)(stage + r * PAD + t * 8);
            *(uint4*)(g_h2h + (size_t)(row0 + r) * 256 + bc * 128 + t * 8) = v;
        }
    }
    if (tid < 128) {
        int wcq = tid >> 5, c32 = tid & 31;
        float s = redS[wcq * 32 + c32] + redS[(4 + wcq) * 32 + c32];
        float q = redQ[wcq * 32 + c32] + redQ[(4 + wcq) * 32 + c32];
        atomicAdd(&g_sum2[bc * 128 + tid], s);
        atomicAdd(&g_sumsq2[bc * 128 + tid], q);
    }
}

// ---------------- fc3: fp16 mma (K=256), hfma2_relu bn2, tanh.approx out ------
__global__ void __launch_bounds__(256, 2)
k_fc3(const float* __restrict__ b3,
      const float* __restrict__ bn2g, const float* __restrict__ bn2b,
      float* __restrict__ out, int Bc, float binv) {
    extern __shared__ char dynsm[];
    __half* As = (__half*)dynsm;
    __half* Bs = As + 128 * PAD;
    __shared__ __half2 sc2h[128], sh2h[128];
    __shared__ float b3s[128];

    int tid = threadIdx.x;
    int row0 = blockIdx.x * 128;
    int bc = blockIdx.y;

    if (tid < 128) {   // bn2 params for col pair (2*tid, 2*tid+1), packed half2
        int j0 = 2 * tid, j1 = 2 * tid + 1;
        float m0v = g_sum2[j0] * binv, m1v = g_sum2[j1] * binv;
        float v0 = g_sumsq2[j0] * binv - m0v * m0v;
        float v1 = g_sumsq2[j1] * binv - m1v * m1v;
        float s0 = bn2g[j0] * rsqrtf(v0 + BN_EPS);
        float s1 = bn2g[j1] * rsqrtf(v1 + BN_EPS);
        sc2h[tid] = __floats2half2_rn(s0, s1);
        sh2h[tid] = __floats2half2_rn(bn2b[j0] - s0 * m0v, bn2b[j1] - s1 * m1v);
        b3s[tid] = b3[bc * 128 + tid];
    }

    int lane = tid & 31, wid = tid >> 5;
    int wr = wid >> 2, wc = wid & 3;
    int m0 = wr * 64, n0 = wc * 32;
    int lrow = lane & 7, mat = lane >> 3;
    int rb = (mat & 1) * 8, kb = (mat >> 1) * 8;

    uint32_t aA[4], bA[2];
    #pragma unroll
    for (int i = 0; i < 4; i++)
        aA[i] = smem_u32(As + (m0 + i * 16 + rb + lrow) * PAD + kb);
    #pragma unroll
    for (int j = 0; j < 2; j++)
        bA[j] = smem_u32(Bs + (n0 + j * 16 + rb + lrow) * PAD + kb);

    float acc[4][4][4];
    #pragma unroll
    for (int i = 0; i < 4; i++)
        #pragma unroll
        for (int j = 0; j < 4; j++)
            #pragma unroll
            for (int p = 0; p < 4; p++) acc[i][j][p] = 0.f;

    for (int ck = 0; ck < 2; ck++) {
        __syncthreads();   // ck=0: params staged; ck>0: tiles free
        // B-stage: cp.async fp16 w3
        #pragma unroll
        for (int i = 0; i < 8; i++) {
            int idx = tid + i * 256;
            int n = idx >> 4, t = idx & 15;
            cp_async16(smem_u32(Bs + n * PAD + t * 8),
                       g_w3h + (size_t)(bc * 128 + n) * 256 + ck * 128 + t * 8);
        }
        CP_COMMIT();
        // A-stage: fp16 h2 load + hfma2_relu bn2
        #pragma unroll
        for (int i = 0; i < 8; i++) {
            int idx = tid + i * 256;
            int r = idx >> 4, t = idx & 15;
            int grow = row0 + r;
            uint4 hv = make_uint4(0u, 0u, 0u, 0u);
            if (grow < Bc) {
                hv = *(const uint4*)(g_h2h + (size_t)grow * 256 + ck * 128 + t * 8);
                __half2* hp = (__half2*)&hv;
                int f2 = ck * 64 + t * 4;
                #pragma unroll
                for (int p = 0; p < 4; p++)
                    hp[p] = __hfma2_relu(hp[p], sc2h[f2 + p], sh2h[f2 + p]);
            }
            *(uint4*)(As + r * PAD + (t << 3)) = hv;
        }
        CP_WAIT0();
        __syncthreads();

        #pragma unroll
        for (int s = 0; s < 8; s++) {
            uint32_t a[4][4], b[4][2];
            #pragma unroll
            for (int i = 0; i < 4; i++)
                ldmx4(a[i][0], a[i][1], a[i][2], a[i][3], aA[i] + s * 32);
            #pragma unroll
            for (int j2 = 0; j2 < 2; j2++)
                ldmx4(b[2*j2][0], b[2*j2+1][0], b[2*j2][1], b[2*j2+1][1], bA[j2] + s * 32);
            #pragma unroll
            for (int i = 0; i < 4; i++)
                #pragma unroll
                for (int j = 0; j < 4; j++)
                    mma_f16(acc[i][j], a[i], b[j]);
        }
    }

    // epilogue: +bias, tanh.approx, fp32 staging -> coalesced stores
    __syncthreads();
    float* stagef = (float*)dynsm;            // [128][136] f32 = 69632 B exactly
    #pragma unroll
    for (int i = 0; i < 4; i++) {
        #pragma unroll
        for (int half = 0; half < 2; half++) {
            int rloc = m0 + i * 16 + (lane >> 2) + half * 8;
            #pragma unroll
            for (int j = 0; j < 4; j++) {
                int cloc = n0 + j * 8 + (lane & 3) * 2;
                float2 o;
                o.x = tanh_fast(acc[i][j][half * 2 + 0] + b3s[cloc]);
                o.y = tanh_fast(acc[i][j][half * 2 + 1] + b3s[cloc + 1]);
                *(float2*)(stagef + rloc * 136 + cloc) = o;
            }
        }
    }
    __syncthreads();
    #pragma unroll
    for (int i = 0; i < 16; i++) {
        int idx = tid + i * 256;
        int r = idx >> 5, t = idx & 31;
        if (row0 + r < Bc) {
            float4 v = *(float4*)(stagef + r * 136 + t * 4);
            *(float4*)(out + (size_t)(row0 + r) * 256 + bc * 128 + t * 4) = v;
        }
    }
}

// ---------------- launch ------------------------------------------------------
extern "C" void kernel_launch(void* const* d_in, const int* in_sizes, int n_in,
                              void* d_out, int out_size) {
    const float* x     = (const float*)d_in[0];
    const float* qp    = (const float*)d_in[1];
    const float* fc1_w = (const float*)d_in[2];
    // d_in[3] = fc1_b (cancels in bn1), d_in[7] = fc2_b (cancels in bn2)
    const float* bn1_g = (const float*)d_in[4];
    const float* bn1_b = (const float*)d_in[5];
    const float* fc2_w = (const float*)d_in[6];
    const float* bn2_g = (const float*)d_in[8];
    const float* bn2_b = (const float*)d_in[9];
    const float* fc3_w = (const float*)d_in[10];
    const float* fc3_b = (const float*)d_in[11];
    float* out = (float*)d_out;

    int Bc = in_sizes[0] / 4;
    if (Bc > BMAX) Bc = BMAX;
    float binv = 1.0f / (float)Bc;

    const int SMEM = 2 * 128 * PAD * (int)sizeof(__half);  // 69632 B
    cudaFuncSetAttribute(k_fc2, cudaFuncAttributeMaxDynamicSharedMemorySize, SMEM);
    cudaFuncSetAttribute(k_fc3, cudaFuncAttributeMaxDynamicSharedMemorySize, SMEM);

    k_prep<<<384, 256>>>(fc2_w, fc3_w);
    k_sim<<<(Bc + 255) / 256, 256>>>(x, qp, Bc);

    dim3 gfc((Bc + 127) / 128, 2);
    k_fc2<<<gfc, 256, SMEM>>>(fc1_w, bn1_g, bn1_b, Bc, binv);
    k_fc3<<<gfc, 256, SMEM>>>(fc3_b, bn2_g, bn2_b, out, Bc, binv);
}

// round 7
// speedup vs baseline: 2.7999x; 1.0756x over previous
#include <cuda_runtime.h>
#include <cuda_fp16.h>
#include <math.h>
#include <stdint.h>

#define BMAX 65536
#define BN_EPS 1e-5f
#define PAD 136   // halves per tile row: 272B = 17*16B -> ldmatrix conflict-free

// ---------------- scratch (static device globals) -----------------------------
static __device__ float  g_q[BMAX * 4];
static __device__ __half g_h2h[(size_t)BMAX * 256];    // 32 MB, L2-resident
static __device__ __half g_w2h[256 * 128];
static __device__ __half g_w3h[256 * 256];
static __device__ float g_sumz[4];
static __device__ float g_sumzz[16];
static __device__ float g_sum2[256];
static __device__ float g_sumsq2[256];

// ---------------- PTX helpers --------------------------------------------------
__device__ __forceinline__ uint32_t smem_u32(const void* p) {
    uint32_t a;
    asm("{ .reg .u64 t; cvta.to.shared.u64 t, %1; cvt.u32.u64 %0, t; }" : "=r"(a) : "l"(p));
    return a;
}
__device__ __forceinline__ void ldmx4(uint32_t& d0, uint32_t& d1, uint32_t& d2, uint32_t& d3,
                                      uint32_t addr) {
    asm volatile("ldmatrix.sync.aligned.m8n8.x4.shared.b16 {%0,%1,%2,%3}, [%4];"
                 : "=r"(d0), "=r"(d1), "=r"(d2), "=r"(d3) : "r"(addr));
}
__device__ __forceinline__ void mma_f16(float* c, const uint32_t* a, const uint32_t* b) {
    asm volatile(
        "mma.sync.aligned.m16n8k16.row.col.f32.f16.f16.f32 "
        "{%0,%1,%2,%3}, {%4,%5,%6,%7}, {%8,%9}, {%0,%1,%2,%3};"
        : "+f"(c[0]), "+f"(c[1]), "+f"(c[2]), "+f"(c[3])
        : "r"(a[0]), "r"(a[1]), "r"(a[2]), "r"(a[3]), "r"(b[0]), "r"(b[1]));
}
__device__ __forceinline__ uint32_t pack_half2(float x, float y) {
    __half2 h = __floats2half2_rn(x, y);
    return *(uint32_t*)&h;
}
__device__ __forceinline__ float tanh_fast(float x) {
    float y;
    asm("tanh.approx.f32 %0, %1;" : "=f"(y) : "f"(x));
    return y;
}
__device__ __forceinline__ void cp_async16(uint32_t saddr, const void* gptr) {
    asm volatile("cp.async.ca.shared.global [%0], [%1], 16;" :: "r"(saddr), "l"(gptr));
}
#define CP_COMMIT() asm volatile("cp.async.commit_group;" ::: "memory")
#define CP_WAIT0()  asm volatile("cp.async.wait_group 0;" ::: "memory")

// fragment load for one k16 step (warp tile 64x32)
#define LOAD_FRAGS(ab, bb, s) do {                                              \
    _Pragma("unroll")                                                           \
    for (int _i = 0; _i < 4; _i++)                                              \
        ldmx4((ab)[_i][0], (ab)[_i][1], (ab)[_i][2], (ab)[_i][3],               \
              aA[_i] + (s) * 32);                                               \
    _Pragma("unroll")                                                           \
    for (int _j = 0; _j < 2; _j++)                                              \
        ldmx4((bb)[2*_j][0], (bb)[2*_j+1][0], (bb)[2*_j][1], (bb)[2*_j+1][1],   \
              bA[_j] + (s) * 32);                                               \
} while (0)

// ---------------- prep: zero accumulators + fp16 weight conversion ------------
__global__ void k_prep(const float* __restrict__ w2, const float* __restrict__ w3) {
    int i = blockIdx.x * blockDim.x + threadIdx.x;
    if (i < 256) {
        if (i < 4)  g_sumz[i] = 0.f;
        if (i < 16) g_sumzz[i] = 0.f;
        g_sum2[i] = 0.f; g_sumsq2[i] = 0.f;
    }
    if (i < 32768) g_w2h[i] = __float2half_rn(w2[i]);
    if (i < 98304) g_w3h[i < 65536 ? i : i] = __float2half_rn(w3[i < 65536 ? i : i]);
}

// ---------------- quantum simulator + q statistics ----------------------------
__global__ void k_sim(const float* __restrict__ x, const float* __restrict__ qp, int Bc) {
    int t = blockIdx.x * blockDim.x + threadIdx.x;
    float z[4] = {0.f, 0.f, 0.f, 0.f};
    if (t < Bc) {
        float xr[4];
        #pragma unroll
        for (int i = 0; i < 4; i++) xr[i] = x[t * 4 + i];
        float re[16], im[16];
        #pragma unroll
        for (int i = 0; i < 16; i++) { re[i] = 0.f; im[i] = 0.f; }
        re[0] = 1.f;
        #pragma unroll
        for (int d = 0; d < 3; d++) {
            #pragma unroll
            for (int i = 0; i < 4; i++) {
                float s, c;
                __sincosf(0.5f * (xr[i] + qp[d * 8 + i]), &s, &c);
                int m = 1 << (3 - i);
                #pragma unroll
                for (int idx = 0; idx < 16; idx++) {
                    if ((idx & m) == 0) {
                        int p = idx | m;
                        float a0r = re[idx], a0i = im[idx];
                        float a1r = re[p],  a1i = im[p];
                        re[idx] = c * a0r - s * a1r;  im[idx] = c * a0i - s * a1i;
                        re[p]   = s * a0r + c * a1r;  im[p]   = s * a0i + c * a1i;
                    }
                }
            }
            #pragma unroll
            for (int i = 0; i < 4; i++) {
                int cm = 1 << (3 - i);
                int tm = 1 << (3 - ((i + 1) & 3));
                #pragma unroll
                for (int idx = 0; idx < 16; idx++) {
                    if ((idx & cm) && !(idx & tm)) {
                        int p = idx | tm;
                        float tr = re[idx]; re[idx] = re[p]; re[p] = tr;
                        float ti = im[idx]; im[idx] = im[p]; im[p] = ti;
                    }
                }
            }
            #pragma unroll
            for (int i = 0; i < 4; i++) {
                float s, c;
                __sincosf(0.5f * qp[d * 8 + 4 + i], &s, &c);
                int m = 1 << (3 - i);
                #pragma unroll
                for (int idx = 0; idx < 16; idx++) {
                    float pi = (idx & m) ? s : -s;
                    float r0 = re[idx], i0 = im[idx];
                    re[idx] = r0 * c - i0 * pi;
                    im[idx] = i0 * c + r0 * pi;
                }
            }
        }
        #pragma unroll
        for (int i = 0; i < 4; i++) {
            int m = 1 << (3 - i);
            float acc = 0.f;
            #pragma unroll
            for (int idx = 0; idx < 16; idx++) {
                float p = re[idx] * re[idx] + im[idx] * im[idx];
                acc += (idx & m) ? -p : p;
            }
            z[i] = acc;
        }
        *(float4*)(g_q + (size_t)t * 4) = make_float4(z[0], z[1], z[2], z[3]);
    }
    float vals[20];
    #pragma unroll
    for (int a = 0; a < 4; a++) vals[a] = z[a];
    #pragma unroll
    for (int a = 0; a < 4; a++)
        #pragma unroll
        for (int b = 0; b < 4; b++) vals[4 + a * 4 + b] = z[a] * z[b];
    #pragma unroll
    for (int v = 0; v < 20; v++) {
        #pragma unroll
        for (int off = 16; off > 0; off >>= 1)
            vals[v] += __shfl_xor_sync(0xffffffffu, vals[v], off);
    }
    if ((threadIdx.x & 31) == 0) {
        #pragma unroll
        for (int a = 0; a < 4; a++) atomicAdd(&g_sumz[a], vals[a]);
        #pragma unroll
        for (int v = 0; v < 16; v++) atomicAdd(&g_sumzz[v], vals[4 + v]);
    }
}

// ---------------- fc2: fp16 mma, cp.async B, fused bn1 + bn2 stats ------------
__global__ void __launch_bounds__(256, 2)
k_fc2(const float* __restrict__ w1,
      const float* __restrict__ bn1g, const float* __restrict__ bn1b,
      int Bc, float binv) {
    extern __shared__ char dynsm[];
    __half* As = (__half*)dynsm;             // [128][PAD]
    __half* Bs = As + 128 * PAD;             // [128][PAD]
    __shared__ float qs[512], w1s[512], sc1s[128], sh1s[128];
    __shared__ float redS[8 * 32], redQ[8 * 32];

    int tid = threadIdx.x;
    int row0 = blockIdx.x * 128;
    int bc = blockIdx.y;

    // B-stage: cp.async fp16 weights (no regs, overlaps everything below)
    #pragma unroll
    for (int i = 0; i < 8; i++) {
        int idx = tid + i * 256;
        int n = idx >> 4, t = idx & 15;
        cp_async16(smem_u32(Bs + n * PAD + t * 8),
                   g_w2h + (size_t)(bc * 128 + n) * 128 + t * 8);
    }
    CP_COMMIT();

    // inline bn1 params (analytic; redundant per block, trivial)
    if (tid < 128) {
        int j = tid;
        float mu[4], C[16];
        #pragma unroll
        for (int a = 0; a < 4; a++) mu[a] = g_sumz[a] * binv;
        #pragma unroll
        for (int a = 0; a < 4; a++)
            #pragma unroll
            for (int c = 0; c < 4; c++)
                C[a * 4 + c] = g_sumzz[a * 4 + c] * binv - mu[a] * mu[c];
        float w[4];
        #pragma unroll
        for (int a = 0; a < 4; a++) w[a] = w1[j * 4 + a];
        float m0v = 0.f, v = 0.f;
        #pragma unroll
        for (int a = 0; a < 4; a++) {
            m0v += w[a] * mu[a];
            #pragma unroll
            for (int c = 0; c < 4; c++) v += w[a] * w[c] * C[a * 4 + c];
        }
        float sc = bn1g[j] * rsqrtf(v + BN_EPS);
        sc1s[j] = sc;
        sh1s[j] = bn1b[j] - sc * m0v;
        int r = row0 + j;
        float4 q = (r < Bc) ? *(const float4*)(g_q + (size_t)r * 4)
                            : make_float4(0.f, 0.f, 0.f, 0.f);
        *(float4*)(qs + j * 4) = q;
    }
    w1s[tid] = w1[tid];
    w1s[tid + 256] = w1[tid + 256];
    __syncthreads();

    // A-stage: h1r from q on the fly -> half tile
    #pragma unroll
    for (int i = 0; i < 8; i++) {
        int idx = tid + i * 256;
        int r = idx >> 4, g8 = (idx & 15) << 3;
        bool valid = (row0 + r < Bc);
        float4 qv = *(const float4*)(qs + r * 4);
        uint32_t pk[4];
        #pragma unroll
        for (int p = 0; p < 4; p++) {
            int f0 = g8 + 2 * p, f1 = f0 + 1;
            float d0 = qv.x * w1s[f0 * 4] + qv.y * w1s[f0 * 4 + 1]
                     + qv.z * w1s[f0 * 4 + 2] + qv.w * w1s[f0 * 4 + 3];
            float d1 = qv.x * w1s[f1 * 4] + qv.y * w1s[f1 * 4 + 1]
                     + qv.z * w1s[f1 * 4 + 2] + qv.w * w1s[f1 * 4 + 3];
            float v0 = valid ? fmaxf(fmaf(sc1s[f0], d0, sh1s[f0]), 0.f) : 0.f;
            float v1 = valid ? fmaxf(fmaf(sc1s[f1], d1, sh1s[f1]), 0.f) : 0.f;
            pk[p] = pack_half2(v0, v1);
        }
        *(uint4*)(As + r * PAD + g8) = make_uint4(pk[0], pk[1], pk[2], pk[3]);
    }
    CP_WAIT0();
    __syncthreads();

    int lane = tid & 31, wid = tid >> 5;
    int wr = wid >> 2, wc = wid & 3;
    int m0 = wr * 64, n0 = wc * 32;
    int lrow = lane & 7, mat = lane >> 3;
    int rb = (mat & 1) * 8, kb = (mat >> 1) * 8;

    uint32_t aA[4], bA[2];
    #pragma unroll
    for (int i = 0; i < 4; i++)
        aA[i] = smem_u32(As + (m0 + i * 16 + rb + lrow) * PAD + kb);
    #pragma unroll
    for (int j = 0; j < 2; j++)
        bA[j] = smem_u32(Bs + (n0 + j * 16 + rb + lrow) * PAD + kb);

    float acc[4][4][4];
    #pragma unroll
    for (int i = 0; i < 4; i++)
        #pragma unroll
        for (int j = 0; j < 4; j++)
            #pragma unroll
            for (int p = 0; p < 4; p++) acc[i][j][p] = 0.f;

    // software-pipelined mainloop: prefetch step s+1 frags during step s mmas
    uint32_t afr[2][4][4], bfr[2][4][2];
    LOAD_FRAGS(afr[0], bfr[0], 0);
    #pragma unroll
    for (int s = 0; s < 8; s++) {
        int cur = s & 1, nxt = cur ^ 1;
        if (s < 7) LOAD_FRAGS(afr[nxt], bfr[nxt], s + 1);
        #pragma unroll
        for (int i = 0; i < 4; i++)
            #pragma unroll
            for (int j = 0; j < 4; j++)
                mma_f16(acc[i][j], afr[cur][i], bfr[cur][j]);
    }

    // epilogue: stats + fp16 h2 via smem staging (tiles dead after sync)
    __syncthreads();
    __half* stage = As;
    float cs[4][2], cq[4][2];
    #pragma unroll
    for (int j = 0; j < 4; j++) { cs[j][0] = cs[j][1] = cq[j][0] = cq[j][1] = 0.f; }

    #pragma unroll
    for (int i = 0; i < 4; i++) {
        #pragma unroll
        for (int half = 0; half < 2; half++) {
            int rloc = m0 + i * 16 + (lane >> 2) + half * 8;
            #pragma unroll
            for (int j = 0; j < 4; j++) {
                float v0 = acc[i][j][half * 2 + 0];
                float v1 = acc[i][j][half * 2 + 1];
                int cloc = n0 + j * 8 + (lane & 3) * 2;
                *(uint32_t*)(stage + rloc * PAD + cloc) = pack_half2(v0, v1);
                cs[j][0] += v0; cs[j][1] += v1;
                cq[j][0] += v0 * v0; cq[j][1] += v1 * v1;
            }
        }
    }
    #pragma unroll
    for (int j = 0; j < 4; j++)
        #pragma unroll
        for (int p = 0; p < 2; p++) {
            #pragma unroll
            for (int off = 4; off < 32; off <<= 1) {
                cs[j][p] += __shfl_xor_sync(0xffffffffu, cs[j][p], off);
                cq[j][p] += __shfl_xor_sync(0xffffffffu, cq[j][p], off);
            }
        }
    if (lane < 4) {
        #pragma unroll
        for (int j = 0; j < 4; j++)
            #pragma unroll
            for (int p = 0; p < 2; p++) {
                int c32 = j * 8 + lane * 2 + p;
                redS[wid * 32 + c32] = cs[j][p];
                redQ[wid * 32 + c32] = cq[j][p];
            }
    }
    __syncthreads();

    #pragma unroll
    for (int i = 0; i < 8; i++) {
        int idx = tid + i * 256;
        int r = idx >> 4, t = idx & 15;
        if (row0 + r < Bc) {
            uint4 v = *(uint4*)(stage + r * PAD + t * 8);
            *(uint4*)(g_h2h + (size_t)(row0 + r) * 256 + bc * 128 + t * 8) = v;
        }
    }
    if (tid < 128) {
        int wcq = tid >> 5, c32 = tid & 31;
        float s = redS[wcq * 32 + c32] + redS[(4 + wcq) * 32 + c32];
        float q = redQ[wcq * 32 + c32] + redQ[(4 + wcq) * 32 + c32];
        atomicAdd(&g_sum2[bc * 128 + tid], s);
        atomicAdd(&g_sumsq2[bc * 128 + tid], q);
    }
}

// ---------------- fc3: fp16 mma (K=256), hfma2_relu bn2, tanh.approx out ------
__global__ void __launch_bounds__(256, 2)
k_fc3(const float* __restrict__ b3,
      const float* __restrict__ bn2g, const float* __restrict__ bn2b,
      float* __restrict__ out, int Bc, float binv) {
    extern __shared__ char dynsm[];
    __half* As = (__half*)dynsm;
    __half* Bs = As + 128 * PAD;
    __shared__ __half2 sc2h[128], sh2h[128];
    __shared__ float b3s[128];

    int tid = threadIdx.x;
    int row0 = blockIdx.x * 128;
    int bc = blockIdx.y;

    if (tid < 128) {   // bn2 params for col pair (2*tid, 2*tid+1), packed half2
        int j0 = 2 * tid, j1 = 2 * tid + 1;
        float m0v = g_sum2[j0] * binv, m1v = g_sum2[j1] * binv;
        float v0 = g_sumsq2[j0] * binv - m0v * m0v;
        float v1 = g_sumsq2[j1] * binv - m1v * m1v;
        float s0 = bn2g[j0] * rsqrtf(v0 + BN_EPS);
        float s1 = bn2g[j1] * rsqrtf(v1 + BN_EPS);
        sc2h[tid] = __floats2half2_rn(s0, s1);
        sh2h[tid] = __floats2half2_rn(bn2b[j0] - s0 * m0v, bn2b[j1] - s1 * m1v);
        b3s[tid] = b3[bc * 128 + tid];
    }

    int lane = tid & 31, wid = tid >> 5;
    int wr = wid >> 2, wc = wid & 3;
    int m0 = wr * 64, n0 = wc * 32;
    int lrow = lane & 7, mat = lane >> 3;
    int rb = (mat & 1) * 8, kb = (mat >> 1) * 8;

    uint32_t aA[4], bA[2];
    #pragma unroll
    for (int i = 0; i < 4; i++)
        aA[i] = smem_u32(As + (m0 + i * 16 + rb + lrow) * PAD + kb);
    #pragma unroll
    for (int j = 0; j < 2; j++)
        bA[j] = smem_u32(Bs + (n0 + j * 16 + rb + lrow) * PAD + kb);

    float acc[4][4][4];
    #pragma unroll
    for (int i = 0; i < 4; i++)
        #pragma unroll
        for (int j = 0; j < 4; j++)
            #pragma unroll
            for (int p = 0; p < 4; p++) acc[i][j][p] = 0.f;

    for (int ck = 0; ck < 2; ck++) {
        __syncthreads();   // ck=0: params staged; ck>0: tiles free
        // B-stage: cp.async fp16 w3
        #pragma unroll
        for (int i = 0; i < 8; i++) {
            int idx = tid + i * 256;
            int n = idx >> 4, t = idx & 15;
            cp_async16(smem_u32(Bs + n * PAD + t * 8),
                       g_w3h + (size_t)(bc * 128 + n) * 256 + ck * 128 + t * 8);
        }
        CP_COMMIT();
        // A-stage: fp16 h2 load + hfma2_relu bn2
        #pragma unroll
        for (int i = 0; i < 8; i++) {
            int idx = tid + i * 256;
            int r = idx >> 4, t = idx & 15;
            int grow = row0 + r;
            uint4 hv = make_uint4(0u, 0u, 0u, 0u);
            if (grow < Bc) {
                hv = *(const uint4*)(g_h2h + (size_t)grow * 256 + ck * 128 + t * 8);
                __half2* hp = (__half2*)&hv;
                int f2 = ck * 64 + t * 4;
                #pragma unroll
                for (int p = 0; p < 4; p++)
                    hp[p] = __hfma2_relu(hp[p], sc2h[f2 + p], sh2h[f2 + p]);
            }
            *(uint4*)(As + r * PAD + (t << 3)) = hv;
        }
        CP_WAIT0();
        __syncthreads();

        // software-pipelined mainloop
        uint32_t afr[2][4][4], bfr[2][4][2];
        LOAD_FRAGS(afr[0], bfr[0], 0);
        #pragma unroll
        for (int s = 0; s < 8; s++) {
            int cur = s & 1, nxt = cur ^ 1;
            if (s < 7) LOAD_FRAGS(afr[nxt], bfr[nxt], s + 1);
            #pragma unroll
            for (int i = 0; i < 4; i++)
                #pragma unroll
                for (int j = 0; j < 4; j++)
                    mma_f16(acc[i][j], afr[cur][i], bfr[cur][j]);
        }
    }

    // epilogue: +bias, tanh.approx, fp32 staging -> coalesced stores
    __syncthreads();
    float* stagef = (float*)dynsm;            // [128][136] f32 = 69632 B exactly
    #pragma unroll
    for (int i = 0; i < 4; i++) {
        #pragma unroll
        for (int half = 0; half < 2; half++) {
            int rloc = m0 + i * 16 + (lane >> 2) + half * 8;
            #pragma unroll
            for (int j = 0; j < 4; j++) {
                int cloc = n0 + j * 8 + (lane & 3) * 2;
                float2 o;
                o.x = tanh_fast(acc[i][j][half * 2 + 0] + b3s[cloc]);
                o.y = tanh_fast(acc[i][j][half * 2 + 1] + b3s[cloc + 1]);
                *(float2*)(stagef + rloc * 136 + cloc) = o;
            }
        }
    }
    __syncthreads();
    #pragma unroll
    for (int i = 0; i < 16; i++) {
        int idx = tid + i * 256;
        int r = idx >> 5, t = idx & 31;
        if (row0 + r < Bc) {
            float4 v = *(float4*)(stagef + r * 136 + t * 4);
            *(float4*)(out + (size_t)(row0 + r) * 256 + bc * 128 + t * 4) = v;
        }
    }
}

// ---------------- launch ------------------------------------------------------
extern "C" void kernel_launch(void* const* d_in, const int* in_sizes, int n_in,
                              void* d_out, int out_size) {
    const float* x     = (const float*)d_in[0];
    const float* qp    = (const float*)d_in[1];
    const float* fc1_w = (const float*)d_in[2];
    // d_in[3] = fc1_b (cancels in bn1), d_in[7] = fc2_b (cancels in bn2)
    const float* bn1_g = (const float*)d_in[4];
    const float* bn1_b = (const float*)d_in[5];
    const float* fc2_w = (const float*)d_in[6];
    const float* bn2_g = (const float*)d_in[8];
    const float* bn2_b = (const float*)d_in[9];
    const float* fc3_w = (const float*)d_in[10];
    const float* fc3_b = (const float*)d_in[11];
    float* out = (float*)d_out;

    int Bc = in_sizes[0] / 4;
    if (Bc > BMAX) Bc = BMAX;
    float binv = 1.0f / (float)Bc;

    const int SMEM = 2 * 128 * PAD * (int)sizeof(__half);  // 69632 B
    cudaFuncSetAttribute(k_fc2, cudaFuncAttributeMaxDynamicSharedMemorySize, SMEM);
    cudaFuncSetAttribute(k_fc3, cudaFuncAttributeMaxDynamicSharedMemorySize, SMEM);

    k_prep<<<384, 256>>>(fc2_w, fc3_w);
    k_sim<<<(Bc + 255) / 256, 256>>>(x, qp, Bc);

    dim3 gfc((Bc + 127) / 128, 2);
    k_fc2<<<gfc, 256, SMEM>>>(fc1_w, bn1_g, bn1_b, Bc, binv);
    k_fc3<<<gfc, 256, SMEM>>>(fc3_b, bn2_g, bn2_b, out, Bc, binv);
}